// round 13
// baseline (speedup 1.0000x reference)
#include <cuda_runtime.h>
#include <math.h>

#define B      16384
#define DIN    12
#define HID    192
#define LAYERS 24
#define NB     66
#define CAP2   112

// ---------------- scratch ----------------
__device__ float g_zk[B * DIN];       // final z (k=0) for k_kl
__device__ float g_V [B * 72];
__device__ float g_ld[B];
__device__ float g_part[256];
__device__ float g_ssq;

// ---------------- f32x2 packed ops ----------------
union F2U { float2 f; unsigned long long u; };
__device__ __forceinline__ float2 ffma2(float2 a, float2 b, float2 c) {
    F2U A, Bv, C, D; A.f = a; Bv.f = b; C.f = c;
    asm("fma.rn.f32x2 %0,%1,%2,%3;" : "=l"(D.u) : "l"(A.u), "l"(Bv.u), "l"(C.u));
    return D.f;
}
__device__ __forceinline__ float2 fmul2(float2 a, float2 b) {
    F2U A, Bv, D; A.f = a; Bv.f = b;
    asm("mul.rn.f32x2 %0,%1,%2;" : "=l"(D.u) : "l"(A.u), "l"(Bv.u));
    return D.f;
}
__device__ __forceinline__ float2 fadd2(float2 a, float2 b) {
    F2U A, Bv, D; A.f = a; Bv.f = b;
    asm("add.rn.f32x2 %0,%1,%2;" : "=l"(D.u) : "l"(A.u), "l"(Bv.u));
    return D.f;
}

__device__ __forceinline__ float pick6(const float a[6], int i) {
    float r = a[0];
    if (i == 1) r = a[1];
    if (i == 2) r = a[2];
    if (i == 3) r = a[3];
    if (i == 4) r = a[4];
    if (i == 5) r = a[5];
    return r;
}
__device__ __forceinline__ float2 pick6f2(const float2 a[6], int i) {
    float2 r = a[0];
    if (i == 1) r = a[1];
    if (i == 2) r = a[2];
    if (i == 3) r = a[3];
    if (i == 4) r = a[4];
    if (i == 5) r = a[5];
    return r;
}

// ---------------- init (g_V only) ----------------
__global__ void k_init(const float* __restrict__ Jp) {
    int i0 = blockIdx.x * blockDim.x + threadIdx.x;
    int st = gridDim.x * blockDim.x;
    for (int i = i0; i < B * 72; i += st) g_V[i] = Jp[i];
}

// smem float offsets
#define OFF_W2R  0        // [192][193]: W2R[a*193+b] = W2[a][b]
#define OFF_W3   37056    // paired: float2[6*192]: (W3[2j][c], W3[2j+1][c])
#define OFF_W1T  39360    // [6][192]: W1t[j*192+r] = W1[r][j]
#define OFF_B1   40512
#define OFF_B2   40704
#define OFF_B3   40896    // 16
#define OFF_WARP 40912
#define WSTRIDE  1064
// per-warp floats: [0,896) entries (inv list float2 / vjp packets 2xfloat4, CAP2=112),
//                  [896,968) Vw, [968,1052) zbuf (7 samples x 12), [1052,1060) ldb

// ---------------- persistent fused inverse + VJP over all layers ----------------
__global__ void __launch_bounds__(512) k_fused(
    const float* __restrict__ y,
    const float* __restrict__ W1, const float* __restrict__ b1,
    const float* __restrict__ W2, const float* __restrict__ b2,
    const float* __restrict__ W3, const float* __restrict__ b3)
{
    extern __shared__ float sm[];
    int tid = threadIdx.x;
    int lane = tid & 31, wip = tid >> 5;

    float*  wb   = sm + OFF_WARP + wip * WSTRIDE;
    float2* pw   = (float2*)wb;
    float4* pw4  = (float4*)wb;
    float*  Vw   = wb + 896;
    float*  zbuf = wb + 968;
    float*  ldb  = wb + 1052;
    unsigned lt = (1u << lane) - 1u;

    const float*  w2rl = sm + OFF_W2R + lane * 193;
    const float*  w2rb = sm + OFF_W2R + lane;
    const float2* w3pl = ((const float2*)(sm + OFF_W3)) + lane;
    const float2* w3pb = (const float2*)(sm + OFF_W3);
    const float*  w1tl = sm + OFF_W1T + lane;
    const float*  b1l  = sm + OFF_B1 + lane;
    const float*  b2l  = sm + OFF_B2 + lane;
    const float*  b3s  = sm + OFF_B3;

    int w  = (blockIdx.x * 512 + tid) >> 5;
    int nw = gridDim.x * 16;

    // init per-warp z buffers (y) and logdet accumulators
#pragma unroll
    for (int si = 0; si < 7; si++) {
        int b = w + si * nw;
        if (b < B && lane < 12) zbuf[si * 12 + lane] = y[(size_t)b * 12 + lane];
    }
    if (lane < 7) ldb[lane] = 0.f;

    for (int k = LAYERS - 1; k >= 0; k--) {
        __syncthreads();   // all warps done reading previous layer's weights
        // ---- stage layer-k weights ----
        {
            const float* W2k = W2 + (size_t)k * HID * HID;
            const float* W3k = W3 + (size_t)k * 12 * HID;
            const float* W1k = W1 + (size_t)k * HID * 6;
            const float* b1k = b1 + (size_t)k * HID;
            const float* b2k = b2 + (size_t)k * HID;
            const float* b3k = b3 + (size_t)k * 12;
            for (int i = tid; i < HID * HID; i += 512) {
                int a = i / HID, bb = i % HID;
                sm[OFF_W2R + a * 193 + bb] = W2k[i];
            }
            float2* w3p = (float2*)(sm + OFF_W3);
            for (int i = tid; i < 6 * HID; i += 512) {
                int j = i / HID, col = i % HID;
                w3p[j * 192 + col] = make_float2(W3k[(2 * j) * HID + col],
                                                 W3k[(2 * j + 1) * HID + col]);
            }
            for (int i = tid; i < HID * 6; i += 512) {
                int r = i / 6, j = i % 6;
                sm[OFF_W1T + j * 192 + r] = W1k[i];
            }
            for (int i = tid; i < HID; i += 512) { sm[OFF_B1 + i] = b1k[i]; sm[OFF_B2 + i] = b2k[i]; }
            if (tid < 12) sm[OFF_B3 + tid] = b3k[tid];
        }
        __syncthreads();

        // ---- process this warp's samples ----
#pragma unroll 1
        for (int si = 0; si < 7; si++) {
            int b = w + si * nw;
            if (b >= B) continue;
            float* zs = zbuf + si * 12;

            __syncwarp();
            // hoisted Vw load (hidden behind inverse phase)
            {
                const float* vp = g_V + (size_t)b * 72;
                Vw[lane]      = vp[lane];
                Vw[lane + 32] = vp[lane + 32];
                if (lane < 8) Vw[lane + 64] = vp[lane + 64];
            }
            float z1[6], z2[6];
#pragma unroll
            for (int j = 0; j < 6; j++) { z1[j] = zs[6 + j]; z2[j] = zs[j]; }

            // ===== INVERSE =====
            unsigned mm1[6];
            int base = 0;
#pragma unroll
            for (int i = 0; i < 6; i++) {
                float a = b1l[32 * i];
#pragma unroll
                for (int j = 0; j < 6; j++) a = fmaf(w1tl[j * 192 + 32 * i], z1[j], a);
                unsigned m = __ballot_sync(0xffffffffu, a > 0.f);
                mm1[i] = m;
                if ((m >> lane) & 1u) {
                    int pos = base + __popc(m & lt);
                    pw[pos] = make_float2(a, __int_as_float(lane + 32 * i));
                }
                base += __popc(m);
            }
            int cnt1 = base;
            int pad1 = (-cnt1) & 3;
            if (lane < pad1) pw[cnt1 + lane] = make_float2(0.f, __int_as_float(0));
            int cnt1r = cnt1 + pad1;
            __syncwarp();

            // L2
            float2 hacc[6];
#pragma unroll
            for (int i = 0; i < 6; i++) hacc[i] = make_float2(b2l[32 * i], 0.f);
            for (int c = 0; c < cnt1r; c += 4) {
                float4 L0 = pw4[c >> 1], L1 = pw4[(c >> 1) + 1];
                const float* rp0 = w2rl + __float_as_int(L0.y);
                const float* rp1 = w2rl + __float_as_int(L0.w);
                const float* rp2 = w2rl + __float_as_int(L1.y);
                const float* rp3 = w2rl + __float_as_int(L1.w);
                float2 h01 = make_float2(L0.x, L0.z);
                float2 h23 = make_float2(L1.x, L1.z);
#pragma unroll
                for (int i = 0; i < 6; i++) {
                    hacc[i] = ffma2(make_float2(rp0[6176 * i], rp1[6176 * i]), h01, hacc[i]);
                    hacc[i] = ffma2(make_float2(rp2[6176 * i], rp3[6176 * i]), h23, hacc[i]);
                }
            }
            unsigned mm2[6];
            float h2a[6];
#pragma unroll
            for (int i = 0; i < 6; i++) {
                float hv = hacc[i].x + hacc[i].y;
                mm2[i] = __ballot_sync(0xffffffffu, hv > 0.f);
                h2a[i] = fmaxf(hv, 0.f);
            }

            // L3 via paired W3 (LDS.64)
            float2 shsr[6];
#pragma unroll
            for (int oj = 0; oj < 6; oj++) {
                float2 acc = make_float2(0.f, 0.f);
#pragma unroll
                for (int i = 0; i < 6; i++) {
                    float hv = h2a[i];
                    acc = ffma2(w3pl[oj * 192 + 32 * i], make_float2(hv, hv), acc);
                }
                F2U u; u.f = acc;
#pragma unroll
                for (int off = 16; off > 0; off >>= 1) {
                    F2U o2; o2.u = __shfl_xor_sync(0xffffffffu, u.u, off);
                    u.f = fadd2(u.f, o2.f);
                }
                shsr[oj] = u.f;
            }

            // epilogue
            float ssum = 0.f, znew[6], es[6], fac[6];
#pragma unroll
            for (int j = 0; j < 6; j++) {
                float sh = shsr[j].x + b3s[2 * j];
                float sr = shsr[j].y + b3s[2 * j + 1];
                float s  = 2.f * tanhf(0.5f * sr);
                ssum += s;
                float em = expf(-s);
                znew[j] = (z2[j] - sh) * em;
                es[j]   = expf(s);
                float t2 = 0.5f * s;
                fac[j]  = znew[j] * es[j] * (1.f - t2 * t2);
            }

            // ===== VJP =====
            __syncwarp();
            // commit new z (smem for next layer; global only at k==0)
            if (k > 0) {
                if (lane < 12) zs[lane] = (lane < 6) ? pick6(z1, lane) : pick6(znew, lane - 6);
                if (lane == 31) ldb[si] -= ssum;
            } else {
                if (lane < 12) g_zk[(size_t)b * 12 + lane] =
                    (lane < 6) ? pick6(z1, lane) : pick6(znew, lane - 6);
                if (lane == 31) g_ld[b] = ldb[si] - ssum;
            }

            // step 1 (U-factored, paired W3)
            float2 accv[3][6];
#pragma unroll
            for (int u = 0; u < 3; u++)
#pragma unroll
                for (int i = 0; i < 6; i++) accv[u][i] = make_float2(0.f, 0.f);
#pragma unroll
            for (int j = 0; j < 6; j++) {
                float2 gj[3];
#pragma unroll
                for (int u = 0; u < 3; u++)
                    gj[u] = make_float2(Vw[(2 * u) * 12 + j], Vw[(2 * u + 1) * 12 + j]);
                float fj = fac[j];
#pragma unroll
                for (int i = 0; i < 6; i++) {
                    float2 wp = w3pl[j * 192 + 32 * i];
                    float U = fmaf(fj, wp.y, wp.x);
                    float2 U2 = make_float2(U, U);
#pragma unroll
                    for (int u = 0; u < 3; u++) accv[u][i] = ffma2(gj[u], U2, accv[u][i]);
                }
            }

            // compact m2-active cols into 32B packets
            int pre = 0;
#pragma unroll
            for (int i = 0; i < 6; i++) pre += __popc(mm2[i]);
            bool hasov = (pre > CAP2);
            unsigned ovm[6];
            int base2 = 0;
#pragma unroll
            for (int i = 0; i < 6; i++) {
                unsigned m = mm2[i], keep = m;
                if (hasov) {
                    int pc = __popc(m);
                    int ovc = base2 + pc - CAP2;
                    if (ovc > 0) {
                        if (ovc > pc) ovc = pc;
                        for (int t = 0; t < ovc; t++) keep &= ~(0x80000000u >> __clz(keep));
                    }
                }
                ovm[i] = m ^ keep;
                if ((keep >> lane) & 1u) {
                    int pos = base2 + __popc(keep & lt);
                    int jjoff = (lane + 32 * i) * 193;
                    pw4[pos * 2 + 0] = make_float4(accv[0][i].x, accv[0][i].y, accv[1][i].x, accv[1][i].y);
                    pw4[pos * 2 + 1] = make_float4(accv[2][i].x, accv[2][i].y, __int_as_float(jjoff), 0.f);
                }
                base2 += __popc(keep);
            }
            int cnt2 = base2;
            if ((cnt2 & 1) && lane == 0) {
                pw4[cnt2 * 2 + 0] = make_float4(0.f, 0.f, 0.f, 0.f);
                pw4[cnt2 * 2 + 1] = make_float4(0.f, 0.f, __int_as_float(0), 0.f);
            }
            cnt2 += (cnt2 & 1);
            __syncwarp();

            // main loop: dense output cols lane+32i
            float2 a12[3][6];
#pragma unroll
            for (int u = 0; u < 3; u++)
#pragma unroll
                for (int i = 0; i < 6; i++) a12[u][i] = make_float2(0.f, 0.f);
            for (int c = 0; c < cnt2; c += 2) {
                float4 e0 = pw4[c * 2 + 0], e1 = pw4[c * 2 + 1];
                float4 f0 = pw4[c * 2 + 2], f1 = pw4[c * 2 + 3];
                const float* gp0 = w2rb + __float_as_int(e1.z);
                const float* gp1 = w2rb + __float_as_int(f1.z);
                float2 gA01 = make_float2(e0.x, e0.y);
                float2 gA23 = make_float2(e0.z, e0.w);
                float2 gA45 = make_float2(e1.x, e1.y);
                float2 gB01 = make_float2(f0.x, f0.y);
                float2 gB23 = make_float2(f0.z, f0.w);
                float2 gB45 = make_float2(f1.x, f1.y);
#pragma unroll
                for (int i = 0; i < 6; i++) {
                    float wv0 = gp0[32 * i], wv1 = gp1[32 * i];
                    float2 wd0 = make_float2(wv0, wv0), wd1 = make_float2(wv1, wv1);
                    a12[0][i] = ffma2(gA01, wd0, a12[0][i]);
                    a12[1][i] = ffma2(gA23, wd0, a12[1][i]);
                    a12[2][i] = ffma2(gA45, wd0, a12[2][i]);
                    a12[0][i] = ffma2(gB01, wd1, a12[0][i]);
                    a12[1][i] = ffma2(gB23, wd1, a12[1][i]);
                    a12[2][i] = ffma2(gB45, wd1, a12[2][i]);
                }
            }

            // overflow fallback (exact, rare ~1%): recompute g for dropped cols
            if (hasov) {
#pragma unroll
                for (int i = 0; i < 6; i++) {
                    unsigned ov = ovm[i];
                    while (ov) {
                        int src = __ffs(ov) - 1; ov &= ov - 1;
                        int jj = src + 32 * i;
                        float gg[6];
#pragma unroll
                        for (int v = 0; v < 6; v++) gg[v] = 0.f;
#pragma unroll
                        for (int j = 0; j < 6; j++) {
                            float2 wp = w3pb[j * 192 + jj];
                            float U = fmaf(fac[j], wp.y, wp.x);
#pragma unroll
                            for (int v = 0; v < 6; v++) gg[v] = fmaf(Vw[v * 12 + j], U, gg[v]);
                        }
                        float2 g01 = make_float2(gg[0], gg[1]);
                        float2 g23 = make_float2(gg[2], gg[3]);
                        float2 g45 = make_float2(gg[4], gg[5]);
                        const float* gp = w2rb + jj * 193;
#pragma unroll
                        for (int ii = 0; ii < 6; ii++) {
                            float wv = gp[32 * ii];
                            float2 wd = make_float2(wv, wv);
                            a12[0][ii] = ffma2(g01, wd, a12[0][ii]);
                            a12[1][ii] = ffma2(g23, wd, a12[1][ii]);
                            a12[2][ii] = ffma2(g45, wd, a12[2][ii]);
                        }
                    }
                }
            }

            // mask (mm1) then fold through W1t
            float2 pz2[3][6];
#pragma unroll
            for (int u = 0; u < 3; u++)
#pragma unroll
                for (int j = 0; j < 6; j++) pz2[u][j] = make_float2(0.f, 0.f);
#pragma unroll
            for (int i = 0; i < 6; i++) {
                float mi = ((mm1[i] >> lane) & 1u) ? 1.f : 0.f;
                float2 md = make_float2(mi, mi);
                float2 am0 = fmul2(a12[0][i], md);
                float2 am1 = fmul2(a12[1][i], md);
                float2 am2 = fmul2(a12[2][i], md);
#pragma unroll
                for (int j = 0; j < 6; j++) {
                    float wv = w1tl[j * 192 + 32 * i];
                    float2 wd = make_float2(wv, wv);
                    pz2[0][j] = ffma2(am0, wd, pz2[0][j]);
                    pz2[1][j] = ffma2(am1, wd, pz2[1][j]);
                    pz2[2][j] = ffma2(am2, wd, pz2[2][j]);
                }
            }

            // butterfly reduce
#pragma unroll
            for (int u = 0; u < 3; u++)
#pragma unroll
                for (int j = 0; j < 6; j++) {
                    F2U u2; u2.f = pz2[u][j];
#pragma unroll
                    for (int off = 16; off > 0; off >>= 1) {
                        F2U o2; o2.u = __shfl_xor_sync(0xffffffffu, u2.u, off);
                        u2.f = fadd2(u2.f, o2.f);
                    }
                    pz2[u][j] = u2.f;
                }

            // parallel write: lane j < 6 writes column j
            if (lane < 6) {
                int j = lane;
                float esj = pick6(es, j);
                float* vo = g_V + (size_t)b * 72;
#pragma unroll
                for (int u = 0; u < 3; u++) {
                    float2 pzv = pick6f2(pz2[u], j);
                    vo[(2 * u) * 12 + j]         = Vw[(2 * u) * 12 + 6 + j] + pzv.x;
                    vo[(2 * u) * 12 + 6 + j]     = Vw[(2 * u) * 12 + j] * esj;
                    vo[(2 * u + 1) * 12 + j]     = Vw[(2 * u + 1) * 12 + 6 + j] + pzv.y;
                    vo[(2 * u + 1) * 12 + 6 + j] = Vw[(2 * u + 1) * 12 + j] * esj;
                }
            }
        }
    }
}

// ---------------- deterministic Frobenius-norm reduction ----------------
__global__ void k_ssq_part() {
    float s = 0.f;
    for (int i = blockIdx.x * blockDim.x + threadIdx.x; i < B * 72; i += gridDim.x * blockDim.x) {
        float v = g_V[i]; s += v * v;
    }
    __shared__ float red[256];
    red[threadIdx.x] = s; __syncthreads();
    for (int o = 128; o > 0; o >>= 1) {
        if (threadIdx.x < o) red[threadIdx.x] += red[threadIdx.x + o];
        __syncthreads();
    }
    if (threadIdx.x == 0) g_part[blockIdx.x] = red[0];
}
__global__ void k_ssq_final() {
    __shared__ float red[256];
    red[threadIdx.x] = g_part[threadIdx.x]; __syncthreads();
    for (int o = 128; o > 0; o >>= 1) {
        if (threadIdx.x < o) red[threadIdx.x] += red[threadIdx.x + o];
        __syncthreads();
    }
    if (threadIdx.x == 0) g_ssq = red[0];
}

// ---------------- KL + log_prob: 4 lanes per sample (m-split) ----------------
#define LIX(r, c) ((r) * ((r) + 1) / 2 + (c))
#define ASTR 148

__global__ void __launch_bounds__(128) k_kl(
    const float* __restrict__ Wsym, const float* __restrict__ lvd,
    float* __restrict__ out)
{
    __shared__ float As[NB * ASTR];
    int tid = threadIdx.x;
    for (int i = tid; i < NB * 144; i += 128) {
        int m = i / 144; int rc = i % 144; int r = rc / 12; int c = rc % 12;
        As[m * ASTR + rc] = Wsym[m * 144 + r * 12 + c] - Wsym[m * 144 + c * 12 + r];
    }
    __syncthreads();

    int gid = blockIdx.x * 128 + tid;
    int s   = gid >> 2;
    int sub = gid & 3;
    if (s >= B) return;

    float zr[12]; float zz = 0.f;
#pragma unroll
    for (int i = 0; i < 12; i++) { zr[i] = g_zk[(size_t)s * 12 + i]; zz += zr[i] * zr[i]; }
    float2 zr2[6];
#pragma unroll
    for (int p = 0; p < 6; p++) zr2[p] = make_float2(zr[2 * p], zr[2 * p + 1]);

    float scale = rsqrtf(g_ssq);
    float Jp[6][12];
#pragma unroll
    for (int v = 0; v < 6; v++)
#pragma unroll
        for (int i = 0; i < 12; i++) Jp[v][i] = g_V[(size_t)s * 72 + v * 12 + i] * scale;

    float Sql[78];
#pragma unroll
    for (int i = 0; i < 78; i++) Sql[i] = 0.f;
    float trq = 0.f, trpq = 0.f;

    for (int m = sub; m < NB; m += 4) {
        const float* Am = As + m * ASTR;
        float Jq[12];
#pragma unroll
        for (int jj = 0; jj < 12; jj++) {
            float2 a2 = make_float2(0.f, 0.f);
#pragma unroll
            for (int ip = 0; ip < 6; ip++)
                a2 = ffma2(*(const float2*)(Am + jj * 12 + 2 * ip), zr2[ip], a2);
            float a = a2.x + a2.y;
            Jq[jj] = a; trq = fmaf(a, a, trq);
        }
#pragma unroll
        for (int n = 0; n < 12; n++)
#pragma unroll
            for (int mm = 0; mm <= n; mm++) Sql[LIX(n, mm)] = fmaf(Jq[n], Jq[mm], Sql[LIX(n, mm)]);
#pragma unroll
        for (int v = 0; v < 6; v++) {
            float2 d2 = make_float2(0.f, 0.f);
#pragma unroll
            for (int ip = 0; ip < 6; ip++)
                d2 = ffma2(make_float2(Jp[v][2 * ip], Jp[v][2 * ip + 1]),
                           make_float2(Jq[2 * ip], Jq[2 * ip + 1]), d2);
            float d = d2.x + d2.y;
            trpq = fmaf(d, d, trpq);
        }
    }

#pragma unroll
    for (int i = 0; i < 78; i += 2) {
        F2U u; u.f = make_float2(Sql[i], Sql[i + 1]);
        F2U o1; o1.u = __shfl_xor_sync(0xffffffffu, u.u, 1); u.f = fadd2(u.f, o1.f);
        F2U o2; o2.u = __shfl_xor_sync(0xffffffffu, u.u, 2); u.f = fadd2(u.f, o2.f);
        Sql[i] = u.f.x; Sql[i + 1] = u.f.y;
    }
    {
        F2U u; u.f = make_float2(trq, trpq);
        F2U o1; o1.u = __shfl_xor_sync(0xffffffffu, u.u, 1); u.f = fadd2(u.f, o1.f);
        F2U o2; o2.u = __shfl_xor_sync(0xffffffffu, u.u, 2); u.f = fadd2(u.f, o2.f);
        trq = u.f.x; trpq = u.f.y;
    }
    if (sub != 0) return;

    out[s] = g_ld[s] - 6.f * 1.8378770664093453f - 0.5f * zz;

    float Ml[21];
#pragma unroll
    for (int a = 0; a < 6; a++)
#pragma unroll
        for (int c = 0; c <= a; c++) {
            float acc = 0.f;
#pragma unroll
            for (int i = 0; i < 12; i++) acc = fmaf(Jp[a][i], Jp[c][i], acc);
            Ml[LIX(a, c)] = acc;
        }
#pragma unroll
    for (int d = 0; d < 6; d++) Ml[LIX(d, d)] += 1e-3f;
    float dm = 0.f;
#pragma unroll
    for (int d = 0; d < 6; d++) dm += Ml[LIX(d, d)];
    float normM = fmaxf(dm * (1.f / 6.f), 1e-6f);
#pragma unroll
    for (int d = 0; d < 6; d++) Ml[LIX(d, d)] += 1e-3f * normM;

    float D[12];
#pragma unroll
    for (int i = 0; i < 12; i++) D[i] = expf(-lvd[i]);
#pragma unroll
    for (int d = 0; d < 12; d++) Sql[LIX(d, d)] += D[d];
    float dh = 0.f;
#pragma unroll
    for (int d = 0; d < 12; d++) dh += Sql[LIX(d, d)];
    float normH = fmaxf(dh * (1.f / 12.f), 1e-6f);
#pragma unroll
    for (int d = 0; d < 12; d++) Sql[LIX(d, d)] += 1e-3f * normH;

    float Db[12], sumDb = 0.f;
#pragma unroll
    for (int i = 0; i < 12; i++) { Db[i] = D[i] + 1e-3f * normH; sumDb += Db[i]; }

    float trp = 0.f;
#pragma unroll
    for (int v = 0; v < 6; v++)
#pragma unroll
        for (int i = 0; i < 12; i++) trp = fmaf(Jp[v][i] * Jp[v][i], Db[i], trp);

    float trace = (1e-3f + 1e-3f * normM) * (sumDb + trq) + trp + trpq;

    float ldM = 0.f;
#pragma unroll
    for (int c = 0; c < 6; c++) {
        float d = Ml[LIX(c, c)];
#pragma unroll
        for (int kk = 0; kk < c; kk++) d -= Ml[LIX(c, kk)] * Ml[LIX(c, kk)];
        d = sqrtf(d); ldM += 2.f * logf(d);
        float inv = 1.f / d;
#pragma unroll
        for (int r = c + 1; r < 6; r++) {
            float a = Ml[LIX(r, c)];
#pragma unroll
            for (int kk = 0; kk < c; kk++) a -= Ml[LIX(r, kk)] * Ml[LIX(c, kk)];
            Ml[LIX(r, c)] = a * inv;
        }
    }
    float ldH = 0.f;
#pragma unroll
    for (int c = 0; c < 12; c++) {
        float d = Sql[LIX(c, c)];
#pragma unroll
        for (int kk = 0; kk < c; kk++) d -= Sql[LIX(c, kk)] * Sql[LIX(c, kk)];
        d = sqrtf(d); ldH += 2.f * logf(d);
        float inv = 1.f / d;
#pragma unroll
        for (int r = c + 1; r < 12; r++) {
            float a = Sql[LIX(r, c)];
#pragma unroll
            for (int kk = 0; kk < c; kk++) a -= Sql[LIX(r, kk)] * Sql[LIX(c, kk)];
            Sql[LIX(r, c)] = a * inv;
        }
    }

    float logdet_p = ldM + 6.f * (-6.907755278982137f);
    out[B + s] = 0.5f * (trace - logdet_p - ldH - 12.f);
}

// ---------------- host launcher ----------------
extern "C" void kernel_launch(void* const* d_in, const int* in_sizes, int n_in,
                              void* d_out, int out_size) {
    const float* y    = (const float*)d_in[0];
    const float* Jp   = (const float*)d_in[1];
    const float* W1   = (const float*)d_in[2];
    const float* b1   = (const float*)d_in[3];
    const float* W2   = (const float*)d_in[4];
    const float* b2   = (const float*)d_in[5];
    const float* W3   = (const float*)d_in[6];
    const float* b3   = (const float*)d_in[7];
    const float* Wsym = (const float*)d_in[8];
    const float* lvd  = (const float*)d_in[9];
    float* out = (float*)d_out;

    const int SMEM_F = (OFF_WARP + 16 * WSTRIDE) * 4;  // 231,744 B
    cudaFuncSetAttribute(k_fused, cudaFuncAttributeMaxDynamicSharedMemorySize, SMEM_F);

    k_init<<<256, 256>>>(Jp);
    k_fused<<<152, 512, SMEM_F>>>(y, W1, b1, W2, b2, W3, b3);
    k_ssq_part<<<256, 256>>>();
    k_ssq_final<<<1, 256>>>();
    k_kl<<<(B * 4) / 128, 128>>>(Wsym, lvd, out);
}

// round 14
// speedup vs baseline: 1.0004x; 1.0004x over previous
#include <cuda_runtime.h>
#include <math.h>

#define B      16384
#define DIN    12
#define HID    192
#define LAYERS 24
#define NB     66
#define CAP2   112

// ---------------- scratch ----------------
__device__ float g_zk[B * DIN];       // final z (k=0) for k_kl
__device__ float g_V [B * 72];
__device__ float g_ld[B];
__device__ float g_part[256];
__device__ float g_ssq;

// ---------------- f32x2 packed ops ----------------
union F2U { float2 f; unsigned long long u; };
__device__ __forceinline__ float2 ffma2(float2 a, float2 b, float2 c) {
    F2U A, Bv, C, D; A.f = a; Bv.f = b; C.f = c;
    asm("fma.rn.f32x2 %0,%1,%2,%3;" : "=l"(D.u) : "l"(A.u), "l"(Bv.u), "l"(C.u));
    return D.f;
}
__device__ __forceinline__ float2 fmul2(float2 a, float2 b) {
    F2U A, Bv, D; A.f = a; Bv.f = b;
    asm("mul.rn.f32x2 %0,%1,%2;" : "=l"(D.u) : "l"(A.u), "l"(Bv.u));
    return D.f;
}
__device__ __forceinline__ float2 fadd2(float2 a, float2 b) {
    F2U A, Bv, D; A.f = a; Bv.f = b;
    asm("add.rn.f32x2 %0,%1,%2;" : "=l"(D.u) : "l"(A.u), "l"(Bv.u));
    return D.f;
}

__device__ __forceinline__ float pick6(const float a[6], int i) {
    float r = a[0];
    if (i == 1) r = a[1];
    if (i == 2) r = a[2];
    if (i == 3) r = a[3];
    if (i == 4) r = a[4];
    if (i == 5) r = a[5];
    return r;
}
__device__ __forceinline__ float2 pick6f2(const float2 a[6], int i) {
    float2 r = a[0];
    if (i == 1) r = a[1];
    if (i == 2) r = a[2];
    if (i == 3) r = a[3];
    if (i == 4) r = a[4];
    if (i == 5) r = a[5];
    return r;
}

// ---------------- init (g_V only) ----------------
__global__ void k_init(const float* __restrict__ Jp) {
    int i0 = blockIdx.x * blockDim.x + threadIdx.x;
    int st = gridDim.x * blockDim.x;
    for (int i = i0; i < B * 72; i += st) g_V[i] = Jp[i];
}

// smem float offsets
#define OFF_W2R  0        // [192][193]: W2R[a*193+b] = W2[a][b]
#define OFF_W3   37056    // paired: float2[6*192]: (W3[2j][c], W3[2j+1][c])
#define OFF_W1T  39360    // [6][192]: W1t[j*192+r] = W1[r][j]
#define OFF_B1   40512
#define OFF_B2   40704
#define OFF_B3   40896    // 16
#define OFF_WARP 40912
#define WSTRIDE  1064
// per-warp floats: [0,896) entries (inv list float2 / vjp packets 2xfloat4, CAP2=112),
//                  [896,968) Vw, [968,1052) zbuf (7 samples x 12), [1052,1060) ldb

// ---------------- persistent fused inverse + VJP over all layers ----------------
__global__ void __launch_bounds__(512) k_fused(
    const float* __restrict__ y,
    const float* __restrict__ W1, const float* __restrict__ b1,
    const float* __restrict__ W2, const float* __restrict__ b2,
    const float* __restrict__ W3, const float* __restrict__ b3)
{
    extern __shared__ float sm[];
    int tid = threadIdx.x;
    int lane = tid & 31, wip = tid >> 5;

    float*  wb   = sm + OFF_WARP + wip * WSTRIDE;
    float2* pw   = (float2*)wb;
    float4* pw4  = (float4*)wb;
    float*  Vw   = wb + 896;
    float*  zbuf = wb + 968;
    float*  ldb  = wb + 1052;
    unsigned lt = (1u << lane) - 1u;

    const float*  w2rl = sm + OFF_W2R + lane * 193;
    const float*  w2rb = sm + OFF_W2R + lane;
    const float2* w3pl = ((const float2*)(sm + OFF_W3)) + lane;
    const float2* w3pb = (const float2*)(sm + OFF_W3);
    const float*  w1tl = sm + OFF_W1T + lane;
    const float*  b1l  = sm + OFF_B1 + lane;
    const float*  b2l  = sm + OFF_B2 + lane;
    const float*  b3s  = sm + OFF_B3;

    int w  = (blockIdx.x * 512 + tid) >> 5;
    int nw = gridDim.x * 16;

    // init per-warp z buffers (y) and logdet accumulators
#pragma unroll
    for (int si = 0; si < 7; si++) {
        int b = w + si * nw;
        if (b < B && lane < 12) zbuf[si * 12 + lane] = y[(size_t)b * 12 + lane];
    }
    if (lane < 7) ldb[lane] = 0.f;

    for (int k = LAYERS - 1; k >= 0; k--) {
        __syncthreads();   // all warps done reading previous layer's weights
        // ---- stage layer-k weights ----
        {
            const float* W2k = W2 + (size_t)k * HID * HID;
            const float* W3k = W3 + (size_t)k * 12 * HID;
            const float* W1k = W1 + (size_t)k * HID * 6;
            const float* b1k = b1 + (size_t)k * HID;
            const float* b2k = b2 + (size_t)k * HID;
            const float* b3k = b3 + (size_t)k * 12;
            for (int i = tid; i < HID * HID; i += 512) {
                int a = i / HID, bb = i % HID;
                sm[OFF_W2R + a * 193 + bb] = W2k[i];
            }
            float2* w3p = (float2*)(sm + OFF_W3);
            for (int i = tid; i < 6 * HID; i += 512) {
                int j = i / HID, col = i % HID;
                w3p[j * 192 + col] = make_float2(W3k[(2 * j) * HID + col],
                                                 W3k[(2 * j + 1) * HID + col]);
            }
            for (int i = tid; i < HID * 6; i += 512) {
                int r = i / 6, j = i % 6;
                sm[OFF_W1T + j * 192 + r] = W1k[i];
            }
            for (int i = tid; i < HID; i += 512) { sm[OFF_B1 + i] = b1k[i]; sm[OFF_B2 + i] = b2k[i]; }
            if (tid < 12) sm[OFF_B3 + tid] = b3k[tid];
        }
        __syncthreads();

        // ---- process this warp's samples ----
#pragma unroll 1
        for (int si = 0; si < 7; si++) {
            int b = w + si * nw;
            if (b >= B) continue;
            float* zs = zbuf + si * 12;

            __syncwarp();
            // hoisted Vw load (hidden behind inverse phase)
            {
                const float* vp = g_V + (size_t)b * 72;
                Vw[lane]      = vp[lane];
                Vw[lane + 32] = vp[lane + 32];
                if (lane < 8) Vw[lane + 64] = vp[lane + 64];
            }
            float z1[6], z2[6];
#pragma unroll
            for (int j = 0; j < 6; j++) { z1[j] = zs[6 + j]; z2[j] = zs[j]; }

            // ===== INVERSE =====
            unsigned mm1[6];
            int base = 0;
#pragma unroll
            for (int i = 0; i < 6; i++) {
                float a = b1l[32 * i];
#pragma unroll
                for (int j = 0; j < 6; j++) a = fmaf(w1tl[j * 192 + 32 * i], z1[j], a);
                unsigned m = __ballot_sync(0xffffffffu, a > 0.f);
                mm1[i] = m;
                if ((m >> lane) & 1u) {
                    int pos = base + __popc(m & lt);
                    pw[pos] = make_float2(a, __int_as_float(lane + 32 * i));
                }
                base += __popc(m);
            }
            int cnt1 = base;
            int pad1 = (-cnt1) & 3;
            if (lane < pad1) pw[cnt1 + lane] = make_float2(0.f, __int_as_float(0));
            int cnt1r = cnt1 + pad1;
            __syncwarp();

            // L2
            float2 hacc[6];
#pragma unroll
            for (int i = 0; i < 6; i++) hacc[i] = make_float2(b2l[32 * i], 0.f);
            for (int c = 0; c < cnt1r; c += 4) {
                float4 L0 = pw4[c >> 1], L1 = pw4[(c >> 1) + 1];
                const float* rp0 = w2rl + __float_as_int(L0.y);
                const float* rp1 = w2rl + __float_as_int(L0.w);
                const float* rp2 = w2rl + __float_as_int(L1.y);
                const float* rp3 = w2rl + __float_as_int(L1.w);
                float2 h01 = make_float2(L0.x, L0.z);
                float2 h23 = make_float2(L1.x, L1.z);
#pragma unroll
                for (int i = 0; i < 6; i++) {
                    hacc[i] = ffma2(make_float2(rp0[6176 * i], rp1[6176 * i]), h01, hacc[i]);
                    hacc[i] = ffma2(make_float2(rp2[6176 * i], rp3[6176 * i]), h23, hacc[i]);
                }
            }
            unsigned mm2[6];
            float h2a[6];
#pragma unroll
            for (int i = 0; i < 6; i++) {
                float hv = hacc[i].x + hacc[i].y;
                mm2[i] = __ballot_sync(0xffffffffu, hv > 0.f);
                h2a[i] = fmaxf(hv, 0.f);
            }

            // L3 via paired W3 (LDS.64)
            float2 shsr[6];
#pragma unroll
            for (int oj = 0; oj < 6; oj++) {
                float2 acc = make_float2(0.f, 0.f);
#pragma unroll
                for (int i = 0; i < 6; i++) {
                    float hv = h2a[i];
                    acc = ffma2(w3pl[oj * 192 + 32 * i], make_float2(hv, hv), acc);
                }
                F2U u; u.f = acc;
#pragma unroll
                for (int off = 16; off > 0; off >>= 1) {
                    F2U o2; o2.u = __shfl_xor_sync(0xffffffffu, u.u, off);
                    u.f = fadd2(u.f, o2.f);
                }
                shsr[oj] = u.f;
            }

            // epilogue
            float ssum = 0.f, znew[6], es[6], fac[6];
#pragma unroll
            for (int j = 0; j < 6; j++) {
                float sh = shsr[j].x + b3s[2 * j];
                float sr = shsr[j].y + b3s[2 * j + 1];
                float s  = 2.f * tanhf(0.5f * sr);
                ssum += s;
                float em = expf(-s);
                znew[j] = (z2[j] - sh) * em;
                es[j]   = expf(s);
                float t2 = 0.5f * s;
                fac[j]  = znew[j] * es[j] * (1.f - t2 * t2);
            }

            // ===== VJP =====
            __syncwarp();
            // commit new z (smem for next layer; global only at k==0)
            if (k > 0) {
                if (lane < 12) zs[lane] = (lane < 6) ? pick6(z1, lane) : pick6(znew, lane - 6);
                if (lane == 31) ldb[si] -= ssum;
            } else {
                if (lane < 12) g_zk[(size_t)b * 12 + lane] =
                    (lane < 6) ? pick6(z1, lane) : pick6(znew, lane - 6);
                if (lane == 31) g_ld[b] = ldb[si] - ssum;
            }

            // step 1 (U-factored, paired W3)
            float2 accv[3][6];
#pragma unroll
            for (int u = 0; u < 3; u++)
#pragma unroll
                for (int i = 0; i < 6; i++) accv[u][i] = make_float2(0.f, 0.f);
#pragma unroll
            for (int j = 0; j < 6; j++) {
                float2 gj[3];
#pragma unroll
                for (int u = 0; u < 3; u++)
                    gj[u] = make_float2(Vw[(2 * u) * 12 + j], Vw[(2 * u + 1) * 12 + j]);
                float fj = fac[j];
#pragma unroll
                for (int i = 0; i < 6; i++) {
                    float2 wp = w3pl[j * 192 + 32 * i];
                    float U = fmaf(fj, wp.y, wp.x);
                    float2 U2 = make_float2(U, U);
#pragma unroll
                    for (int u = 0; u < 3; u++) accv[u][i] = ffma2(gj[u], U2, accv[u][i]);
                }
            }

            // compact m2-active cols into 32B packets
            int pre = 0;
#pragma unroll
            for (int i = 0; i < 6; i++) pre += __popc(mm2[i]);
            bool hasov = (pre > CAP2);
            unsigned ovm[6];
            int base2 = 0;
#pragma unroll
            for (int i = 0; i < 6; i++) {
                unsigned m = mm2[i], keep = m;
                if (hasov) {
                    int pc = __popc(m);
                    int ovc = base2 + pc - CAP2;
                    if (ovc > 0) {
                        if (ovc > pc) ovc = pc;
                        for (int t = 0; t < ovc; t++) keep &= ~(0x80000000u >> __clz(keep));
                    }
                }
                ovm[i] = m ^ keep;
                if ((keep >> lane) & 1u) {
                    int pos = base2 + __popc(keep & lt);
                    int jjoff = (lane + 32 * i) * 193;
                    pw4[pos * 2 + 0] = make_float4(accv[0][i].x, accv[0][i].y, accv[1][i].x, accv[1][i].y);
                    pw4[pos * 2 + 1] = make_float4(accv[2][i].x, accv[2][i].y, __int_as_float(jjoff), 0.f);
                }
                base2 += __popc(keep);
            }
            int cnt2 = base2;
            if ((cnt2 & 1) && lane == 0) {
                pw4[cnt2 * 2 + 0] = make_float4(0.f, 0.f, 0.f, 0.f);
                pw4[cnt2 * 2 + 1] = make_float4(0.f, 0.f, __int_as_float(0), 0.f);
            }
            cnt2 += (cnt2 & 1);
            __syncwarp();

            // main loop: dense output cols lane+32i
            float2 a12[3][6];
#pragma unroll
            for (int u = 0; u < 3; u++)
#pragma unroll
                for (int i = 0; i < 6; i++) a12[u][i] = make_float2(0.f, 0.f);
            for (int c = 0; c < cnt2; c += 2) {
                float4 e0 = pw4[c * 2 + 0], e1 = pw4[c * 2 + 1];
                float4 f0 = pw4[c * 2 + 2], f1 = pw4[c * 2 + 3];
                const float* gp0 = w2rb + __float_as_int(e1.z);
                const float* gp1 = w2rb + __float_as_int(f1.z);
                float2 gA01 = make_float2(e0.x, e0.y);
                float2 gA23 = make_float2(e0.z, e0.w);
                float2 gA45 = make_float2(e1.x, e1.y);
                float2 gB01 = make_float2(f0.x, f0.y);
                float2 gB23 = make_float2(f0.z, f0.w);
                float2 gB45 = make_float2(f1.x, f1.y);
#pragma unroll
                for (int i = 0; i < 6; i++) {
                    float wv0 = gp0[32 * i], wv1 = gp1[32 * i];
                    float2 wd0 = make_float2(wv0, wv0), wd1 = make_float2(wv1, wv1);
                    a12[0][i] = ffma2(gA01, wd0, a12[0][i]);
                    a12[1][i] = ffma2(gA23, wd0, a12[1][i]);
                    a12[2][i] = ffma2(gA45, wd0, a12[2][i]);
                    a12[0][i] = ffma2(gB01, wd1, a12[0][i]);
                    a12[1][i] = ffma2(gB23, wd1, a12[1][i]);
                    a12[2][i] = ffma2(gB45, wd1, a12[2][i]);
                }
            }

            // overflow fallback (exact, rare ~1%): recompute g for dropped cols
            if (hasov) {
#pragma unroll
                for (int i = 0; i < 6; i++) {
                    unsigned ov = ovm[i];
                    while (ov) {
                        int src = __ffs(ov) - 1; ov &= ov - 1;
                        int jj = src + 32 * i;
                        float gg[6];
#pragma unroll
                        for (int v = 0; v < 6; v++) gg[v] = 0.f;
#pragma unroll
                        for (int j = 0; j < 6; j++) {
                            float2 wp = w3pb[j * 192 + jj];
                            float U = fmaf(fac[j], wp.y, wp.x);
#pragma unroll
                            for (int v = 0; v < 6; v++) gg[v] = fmaf(Vw[v * 12 + j], U, gg[v]);
                        }
                        float2 g01 = make_float2(gg[0], gg[1]);
                        float2 g23 = make_float2(gg[2], gg[3]);
                        float2 g45 = make_float2(gg[4], gg[5]);
                        const float* gp = w2rb + jj * 193;
#pragma unroll
                        for (int ii = 0; ii < 6; ii++) {
                            float wv = gp[32 * ii];
                            float2 wd = make_float2(wv, wv);
                            a12[0][ii] = ffma2(g01, wd, a12[0][ii]);
                            a12[1][ii] = ffma2(g23, wd, a12[1][ii]);
                            a12[2][ii] = ffma2(g45, wd, a12[2][ii]);
                        }
                    }
                }
            }

            // mask (mm1) then fold through W1t
            float2 pz2[3][6];
#pragma unroll
            for (int u = 0; u < 3; u++)
#pragma unroll
                for (int j = 0; j < 6; j++) pz2[u][j] = make_float2(0.f, 0.f);
#pragma unroll
            for (int i = 0; i < 6; i++) {
                float mi = ((mm1[i] >> lane) & 1u) ? 1.f : 0.f;
                float2 md = make_float2(mi, mi);
                float2 am0 = fmul2(a12[0][i], md);
                float2 am1 = fmul2(a12[1][i], md);
                float2 am2 = fmul2(a12[2][i], md);
#pragma unroll
                for (int j = 0; j < 6; j++) {
                    float wv = w1tl[j * 192 + 32 * i];
                    float2 wd = make_float2(wv, wv);
                    pz2[0][j] = ffma2(am0, wd, pz2[0][j]);
                    pz2[1][j] = ffma2(am1, wd, pz2[1][j]);
                    pz2[2][j] = ffma2(am2, wd, pz2[2][j]);
                }
            }

            // butterfly reduce
#pragma unroll
            for (int u = 0; u < 3; u++)
#pragma unroll
                for (int j = 0; j < 6; j++) {
                    F2U u2; u2.f = pz2[u][j];
#pragma unroll
                    for (int off = 16; off > 0; off >>= 1) {
                        F2U o2; o2.u = __shfl_xor_sync(0xffffffffu, u2.u, off);
                        u2.f = fadd2(u2.f, o2.f);
                    }
                    pz2[u][j] = u2.f;
                }

            // parallel write: lane j < 6 writes column j
            if (lane < 6) {
                int j = lane;
                float esj = pick6(es, j);
                float* vo = g_V + (size_t)b * 72;
#pragma unroll
                for (int u = 0; u < 3; u++) {
                    float2 pzv = pick6f2(pz2[u], j);
                    vo[(2 * u) * 12 + j]         = Vw[(2 * u) * 12 + 6 + j] + pzv.x;
                    vo[(2 * u) * 12 + 6 + j]     = Vw[(2 * u) * 12 + j] * esj;
                    vo[(2 * u + 1) * 12 + j]     = Vw[(2 * u + 1) * 12 + 6 + j] + pzv.y;
                    vo[(2 * u + 1) * 12 + 6 + j] = Vw[(2 * u + 1) * 12 + j] * esj;
                }
            }
        }
    }
}

// ---------------- deterministic Frobenius-norm reduction ----------------
__global__ void k_ssq_part() {
    float s = 0.f;
    for (int i = blockIdx.x * blockDim.x + threadIdx.x; i < B * 72; i += gridDim.x * blockDim.x) {
        float v = g_V[i]; s += v * v;
    }
    __shared__ float red[256];
    red[threadIdx.x] = s; __syncthreads();
    for (int o = 128; o > 0; o >>= 1) {
        if (threadIdx.x < o) red[threadIdx.x] += red[threadIdx.x + o];
        __syncthreads();
    }
    if (threadIdx.x == 0) g_part[blockIdx.x] = red[0];
}
__global__ void k_ssq_final() {
    __shared__ float red[256];
    red[threadIdx.x] = g_part[threadIdx.x]; __syncthreads();
    for (int o = 128; o > 0; o >>= 1) {
        if (threadIdx.x < o) red[threadIdx.x] += red[threadIdx.x + o];
        __syncthreads();
    }
    if (threadIdx.x == 0) g_ssq = red[0];
}

// ---------------- KL + log_prob: 4 lanes per sample (m-split) ----------------
#define LIX(r, c) ((r) * ((r) + 1) / 2 + (c))
#define ASTR 148

__global__ void __launch_bounds__(128) k_kl(
    const float* __restrict__ Wsym, const float* __restrict__ lvd,
    float* __restrict__ out)
{
    __shared__ float As[NB * ASTR];
    int tid = threadIdx.x;
    for (int i = tid; i < NB * 144; i += 128) {
        int m = i / 144; int rc = i % 144; int r = rc / 12; int c = rc % 12;
        As[m * ASTR + rc] = Wsym[m * 144 + r * 12 + c] - Wsym[m * 144 + c * 12 + r];
    }
    __syncthreads();

    int gid = blockIdx.x * 128 + tid;
    int s   = gid >> 2;
    int sub = gid & 3;
    if (s >= B) return;

    float zr[12]; float zz = 0.f;
#pragma unroll
    for (int i = 0; i < 12; i++) { zr[i] = g_zk[(size_t)s * 12 + i]; zz += zr[i] * zr[i]; }
    float2 zr2[6];
#pragma unroll
    for (int p = 0; p < 6; p++) zr2[p] = make_float2(zr[2 * p], zr[2 * p + 1]);

    float scale = rsqrtf(g_ssq);
    float Jp[6][12];
#pragma unroll
    for (int v = 0; v < 6; v++)
#pragma unroll
        for (int i = 0; i < 12; i++) Jp[v][i] = g_V[(size_t)s * 72 + v * 12 + i] * scale;

    float Sql[78];
#pragma unroll
    for (int i = 0; i < 78; i++) Sql[i] = 0.f;
    float trq = 0.f, trpq = 0.f;

    for (int m = sub; m < NB; m += 4) {
        const float* Am = As + m * ASTR;
        float Jq[12];
#pragma unroll
        for (int jj = 0; jj < 12; jj++) {
            float2 a2 = make_float2(0.f, 0.f);
#pragma unroll
            for (int ip = 0; ip < 6; ip++)
                a2 = ffma2(*(const float2*)(Am + jj * 12 + 2 * ip), zr2[ip], a2);
            float a = a2.x + a2.y;
            Jq[jj] = a; trq = fmaf(a, a, trq);
        }
#pragma unroll
        for (int n = 0; n < 12; n++)
#pragma unroll
            for (int mm = 0; mm <= n; mm++) Sql[LIX(n, mm)] = fmaf(Jq[n], Jq[mm], Sql[LIX(n, mm)]);
#pragma unroll
        for (int v = 0; v < 6; v++) {
            float2 d2 = make_float2(0.f, 0.f);
#pragma unroll
            for (int ip = 0; ip < 6; ip++)
                d2 = ffma2(make_float2(Jp[v][2 * ip], Jp[v][2 * ip + 1]),
                           make_float2(Jq[2 * ip], Jq[2 * ip + 1]), d2);
            float d = d2.x + d2.y;
            trpq = fmaf(d, d, trpq);
        }
    }

#pragma unroll
    for (int i = 0; i < 78; i += 2) {
        F2U u; u.f = make_float2(Sql[i], Sql[i + 1]);
        F2U o1; o1.u = __shfl_xor_sync(0xffffffffu, u.u, 1); u.f = fadd2(u.f, o1.f);
        F2U o2; o2.u = __shfl_xor_sync(0xffffffffu, u.u, 2); u.f = fadd2(u.f, o2.f);
        Sql[i] = u.f.x; Sql[i + 1] = u.f.y;
    }
    {
        F2U u; u.f = make_float2(trq, trpq);
        F2U o1; o1.u = __shfl_xor_sync(0xffffffffu, u.u, 1); u.f = fadd2(u.f, o1.f);
        F2U o2; o2.u = __shfl_xor_sync(0xffffffffu, u.u, 2); u.f = fadd2(u.f, o2.f);
        trq = u.f.x; trpq = u.f.y;
    }
    if (sub != 0) return;

    out[s] = g_ld[s] - 6.f * 1.8378770664093453f - 0.5f * zz;

    float Ml[21];
#pragma unroll
    for (int a = 0; a < 6; a++)
#pragma unroll
        for (int c = 0; c <= a; c++) {
            float acc = 0.f;
#pragma unroll
            for (int i = 0; i < 12; i++) acc = fmaf(Jp[a][i], Jp[c][i], acc);
            Ml[LIX(a, c)] = acc;
        }
#pragma unroll
    for (int d = 0; d < 6; d++) Ml[LIX(d, d)] += 1e-3f;
    float dm = 0.f;
#pragma unroll
    for (int d = 0; d < 6; d++) dm += Ml[LIX(d, d)];
    float normM = fmaxf(dm * (1.f / 6.f), 1e-6f);
#pragma unroll
    for (int d = 0; d < 6; d++) Ml[LIX(d, d)] += 1e-3f * normM;

    float D[12];
#pragma unroll
    for (int i = 0; i < 12; i++) D[i] = expf(-lvd[i]);
#pragma unroll
    for (int d = 0; d < 12; d++) Sql[LIX(d, d)] += D[d];
    float dh = 0.f;
#pragma unroll
    for (int d = 0; d < 12; d++) dh += Sql[LIX(d, d)];
    float normH = fmaxf(dh * (1.f / 12.f), 1e-6f);
#pragma unroll
    for (int d = 0; d < 12; d++) Sql[LIX(d, d)] += 1e-3f * normH;

    float Db[12], sumDb = 0.f;
#pragma unroll
    for (int i = 0; i < 12; i++) { Db[i] = D[i] + 1e-3f * normH; sumDb += Db[i]; }

    float trp = 0.f;
#pragma unroll
    for (int v = 0; v < 6; v++)
#pragma unroll
        for (int i = 0; i < 12; i++) trp = fmaf(Jp[v][i] * Jp[v][i], Db[i], trp);

    float trace = (1e-3f + 1e-3f * normM) * (sumDb + trq) + trp + trpq;

    float ldM = 0.f;
#pragma unroll
    for (int c = 0; c < 6; c++) {
        float d = Ml[LIX(c, c)];
#pragma unroll
        for (int kk = 0; kk < c; kk++) d -= Ml[LIX(c, kk)] * Ml[LIX(c, kk)];
        d = sqrtf(d); ldM += 2.f * logf(d);
        float inv = 1.f / d;
#pragma unroll
        for (int r = c + 1; r < 6; r++) {
            float a = Ml[LIX(r, c)];
#pragma unroll
            for (int kk = 0; kk < c; kk++) a -= Ml[LIX(r, kk)] * Ml[LIX(c, kk)];
            Ml[LIX(r, c)] = a * inv;
        }
    }
    float ldH = 0.f;
#pragma unroll
    for (int c = 0; c < 12; c++) {
        float d = Sql[LIX(c, c)];
#pragma unroll
        for (int kk = 0; kk < c; kk++) d -= Sql[LIX(c, kk)] * Sql[LIX(c, kk)];
        d = sqrtf(d); ldH += 2.f * logf(d);
        float inv = 1.f / d;
#pragma unroll
        for (int r = c + 1; r < 12; r++) {
            float a = Sql[LIX(r, c)];
#pragma unroll
            for (int kk = 0; kk < c; kk++) a -= Sql[LIX(r, kk)] * Sql[LIX(c, kk)];
            Sql[LIX(r, c)] = a * inv;
        }
    }

    float logdet_p = ldM + 6.f * (-6.907755278982137f);
    out[B + s] = 0.5f * (trace - logdet_p - ldH - 12.f);
}

// ---------------- host launcher ----------------
extern "C" void kernel_launch(void* const* d_in, const int* in_sizes, int n_in,
                              void* d_out, int out_size) {
    const float* y    = (const float*)d_in[0];
    const float* Jp   = (const float*)d_in[1];
    const float* W1   = (const float*)d_in[2];
    const float* b1   = (const float*)d_in[3];
    const float* W2   = (const float*)d_in[4];
    const float* b2   = (const float*)d_in[5];
    const float* W3   = (const float*)d_in[6];
    const float* b3   = (const float*)d_in[7];
    const float* Wsym = (const float*)d_in[8];
    const float* lvd  = (const float*)d_in[9];
    float* out = (float*)d_out;

    const int SMEM_F = (OFF_WARP + 16 * WSTRIDE) * 4;  // 231,744 B
    cudaFuncSetAttribute(k_fused, cudaFuncAttributeMaxDynamicSharedMemorySize, SMEM_F);

    k_init<<<256, 256>>>(Jp);
    k_fused<<<152, 512, SMEM_F>>>(y, W1, b1, W2, b2, W3, b3);
    k_ssq_part<<<256, 256>>>();
    k_ssq_final<<<1, 256>>>();
    k_kl<<<(B * 4) / 128, 128>>>(Wsym, lvd, out);
}

// round 15
// speedup vs baseline: 1.0028x; 1.0024x over previous
#include <cuda_runtime.h>
#include <math.h>

#define B      16384
#define DIN    12
#define HID    192
#define LAYERS 24
#define NB     66
#define CAP2   112

// ---------------- scratch ----------------
__device__ float g_zk[B * DIN];       // final z (k=0) for k_kl
__device__ float g_V [B * 72];
__device__ float g_ld[B];
__device__ float g_part[256];
__device__ float g_ssq;

// ---------------- f32x2 packed ops ----------------
union F2U { float2 f; unsigned long long u; };
__device__ __forceinline__ float2 ffma2(float2 a, float2 b, float2 c) {
    F2U A, Bv, C, D; A.f = a; Bv.f = b; C.f = c;
    asm("fma.rn.f32x2 %0,%1,%2,%3;" : "=l"(D.u) : "l"(A.u), "l"(Bv.u), "l"(C.u));
    return D.f;
}
__device__ __forceinline__ float2 fmul2(float2 a, float2 b) {
    F2U A, Bv, D; A.f = a; Bv.f = b;
    asm("mul.rn.f32x2 %0,%1,%2;" : "=l"(D.u) : "l"(A.u), "l"(Bv.u));
    return D.f;
}
__device__ __forceinline__ float2 fadd2(float2 a, float2 b) {
    F2U A, Bv, D; A.f = a; Bv.f = b;
    asm("add.rn.f32x2 %0,%1,%2;" : "=l"(D.u) : "l"(A.u), "l"(Bv.u));
    return D.f;
}

__device__ __forceinline__ float pick6(const float a[6], int i) {
    float r = a[0];
    if (i == 1) r = a[1];
    if (i == 2) r = a[2];
    if (i == 3) r = a[3];
    if (i == 4) r = a[4];
    if (i == 5) r = a[5];
    return r;
}
__device__ __forceinline__ float2 pick6f2(const float2 a[6], int i) {
    float2 r = a[0];
    if (i == 1) r = a[1];
    if (i == 2) r = a[2];
    if (i == 3) r = a[3];
    if (i == 4) r = a[4];
    if (i == 5) r = a[5];
    return r;
}

// ---------------- init (g_V only) ----------------
__global__ void k_init(const float* __restrict__ Jp) {
    int i0 = blockIdx.x * blockDim.x + threadIdx.x;
    int st = gridDim.x * blockDim.x;
    for (int i = i0; i < B * 72; i += st) g_V[i] = Jp[i];
}

// smem float offsets
#define OFF_W2R  0        // [192][193]: W2R[a*193+b] = W2[a][b]
#define OFF_W3   37056    // paired: float2[6*192]: (W3[2j][c], W3[2j+1][c])
#define OFF_W1T  39360    // [6][192]: W1t[j*192+r] = W1[r][j]
#define OFF_B1   40512
#define OFF_B2   40704
#define OFF_B3   40896    // 16
#define OFF_WARP 40912
#define WSTRIDE  1064
// per-warp floats: [0,896) entries (inv list float2 / vjp packets 2xfloat4, CAP2=112),
//                  [896,968) Vw, [968,1052) zbuf (7 samples x 12), [1052,1060) ldb

// ---------------- persistent fused inverse + VJP over all layers ----------------
__global__ void __launch_bounds__(512) k_fused(
    const float* __restrict__ y,
    const float* __restrict__ W1, const float* __restrict__ b1,
    const float* __restrict__ W2, const float* __restrict__ b2,
    const float* __restrict__ W3, const float* __restrict__ b3)
{
    extern __shared__ float sm[];
    int tid = threadIdx.x;
    int lane = tid & 31, wip = tid >> 5;

    float*  wb   = sm + OFF_WARP + wip * WSTRIDE;
    float2* pw   = (float2*)wb;
    float4* pw4  = (float4*)wb;
    float*  Vw   = wb + 896;
    float*  zbuf = wb + 968;
    float*  ldb  = wb + 1052;
    unsigned lt = (1u << lane) - 1u;

    const float*  w2rl = sm + OFF_W2R + lane * 193;
    const float*  w2rb = sm + OFF_W2R + lane;
    const float2* w3pl = ((const float2*)(sm + OFF_W3)) + lane;
    const float2* w3pb = (const float2*)(sm + OFF_W3);
    const float*  w1tl = sm + OFF_W1T + lane;
    const float*  b1l  = sm + OFF_B1 + lane;
    const float*  b2l  = sm + OFF_B2 + lane;
    const float*  b3s  = sm + OFF_B3;

    int w  = (blockIdx.x * 512 + tid) >> 5;
    int nw = gridDim.x * 16;

    // init per-warp z buffers (y) and logdet accumulators
#pragma unroll
    for (int si = 0; si < 7; si++) {
        int b = w + si * nw;
        if (b < B && lane < 12) zbuf[si * 12 + lane] = y[(size_t)b * 12 + lane];
    }
    if (lane < 7) ldb[lane] = 0.f;

    for (int k = LAYERS - 1; k >= 0; k--) {
        __syncthreads();   // all warps done reading previous layer's weights
        // ---- stage layer-k weights ----
        {
            const float* W2k = W2 + (size_t)k * HID * HID;
            const float* W3k = W3 + (size_t)k * 12 * HID;
            const float* W1k = W1 + (size_t)k * HID * 6;
            const float* b1k = b1 + (size_t)k * HID;
            const float* b2k = b2 + (size_t)k * HID;
            const float* b3k = b3 + (size_t)k * 12;
            for (int i = tid; i < HID * HID; i += 512) {
                int a = i / HID, bb = i % HID;
                sm[OFF_W2R + a * 193 + bb] = W2k[i];
            }
            float2* w3p = (float2*)(sm + OFF_W3);
            for (int i = tid; i < 6 * HID; i += 512) {
                int j = i / HID, col = i % HID;
                w3p[j * 192 + col] = make_float2(W3k[(2 * j) * HID + col],
                                                 W3k[(2 * j + 1) * HID + col]);
            }
            for (int i = tid; i < HID * 6; i += 512) {
                int r = i / 6, j = i % 6;
                sm[OFF_W1T + j * 192 + r] = W1k[i];
            }
            for (int i = tid; i < HID; i += 512) { sm[OFF_B1 + i] = b1k[i]; sm[OFF_B2 + i] = b2k[i]; }
            if (tid < 12) sm[OFF_B3 + tid] = b3k[tid];
        }
        __syncthreads();

        // ---- process this warp's samples ----
#pragma unroll 1
        for (int si = 0; si < 7; si++) {
            int b = w + si * nw;
            if (b >= B) continue;
            float* zs = zbuf + si * 12;

            __syncwarp();
            // hoisted Vw load (hidden behind inverse phase)
            {
                const float* vp = g_V + (size_t)b * 72;
                Vw[lane]      = vp[lane];
                Vw[lane + 32] = vp[lane + 32];
                if (lane < 8) Vw[lane + 64] = vp[lane + 64];
            }
            float z1[6], z2[6];
#pragma unroll
            for (int j = 0; j < 6; j++) { z1[j] = zs[6 + j]; z2[j] = zs[j]; }

            // ===== INVERSE =====
            unsigned mm1[6];
            int base = 0;
#pragma unroll
            for (int i = 0; i < 6; i++) {
                float a = b1l[32 * i];
#pragma unroll
                for (int j = 0; j < 6; j++) a = fmaf(w1tl[j * 192 + 32 * i], z1[j], a);
                unsigned m = __ballot_sync(0xffffffffu, a > 0.f);
                mm1[i] = m;
                if ((m >> lane) & 1u) {
                    int pos = base + __popc(m & lt);
                    pw[pos] = make_float2(a, __int_as_float(lane + 32 * i));
                }
                base += __popc(m);
            }
            int cnt1 = base;
            int pad1 = (-cnt1) & 3;
            if (lane < pad1) pw[cnt1 + lane] = make_float2(0.f, __int_as_float(0));
            int cnt1r = cnt1 + pad1;
            __syncwarp();

            // L2
            float2 hacc[6];
#pragma unroll
            for (int i = 0; i < 6; i++) hacc[i] = make_float2(b2l[32 * i], 0.f);
            for (int c = 0; c < cnt1r; c += 4) {
                float4 L0 = pw4[c >> 1], L1 = pw4[(c >> 1) + 1];
                const float* rp0 = w2rl + __float_as_int(L0.y);
                const float* rp1 = w2rl + __float_as_int(L0.w);
                const float* rp2 = w2rl + __float_as_int(L1.y);
                const float* rp3 = w2rl + __float_as_int(L1.w);
                float2 h01 = make_float2(L0.x, L0.z);
                float2 h23 = make_float2(L1.x, L1.z);
#pragma unroll
                for (int i = 0; i < 6; i++) {
                    hacc[i] = ffma2(make_float2(rp0[6176 * i], rp1[6176 * i]), h01, hacc[i]);
                    hacc[i] = ffma2(make_float2(rp2[6176 * i], rp3[6176 * i]), h23, hacc[i]);
                }
            }
            unsigned mm2[6];
            float h2a[6];
#pragma unroll
            for (int i = 0; i < 6; i++) {
                float hv = hacc[i].x + hacc[i].y;
                mm2[i] = __ballot_sync(0xffffffffu, hv > 0.f);
                h2a[i] = fmaxf(hv, 0.f);
            }

            // L3 via paired W3 (LDS.64)
            float2 shsr[6];
#pragma unroll
            for (int oj = 0; oj < 6; oj++) {
                float2 acc = make_float2(0.f, 0.f);
#pragma unroll
                for (int i = 0; i < 6; i++) {
                    float hv = h2a[i];
                    acc = ffma2(w3pl[oj * 192 + 32 * i], make_float2(hv, hv), acc);
                }
                F2U u; u.f = acc;
#pragma unroll
                for (int off = 16; off > 0; off >>= 1) {
                    F2U o2; o2.u = __shfl_xor_sync(0xffffffffu, u.u, off);
                    u.f = fadd2(u.f, o2.f);
                }
                shsr[oj] = u.f;
            }

            // epilogue
            float ssum = 0.f, znew[6], es[6], fac[6];
#pragma unroll
            for (int j = 0; j < 6; j++) {
                float sh = shsr[j].x + b3s[2 * j];
                float sr = shsr[j].y + b3s[2 * j + 1];
                float s  = 2.f * tanhf(0.5f * sr);
                ssum += s;
                float em = expf(-s);
                znew[j] = (z2[j] - sh) * em;
                es[j]   = expf(s);
                float t2 = 0.5f * s;
                fac[j]  = znew[j] * es[j] * (1.f - t2 * t2);
            }

            // ===== VJP =====
            __syncwarp();
            // commit new z (smem for next layer; global only at k==0)
            if (k > 0) {
                if (lane < 12) zs[lane] = (lane < 6) ? pick6(z1, lane) : pick6(znew, lane - 6);
                if (lane == 31) ldb[si] -= ssum;
            } else {
                if (lane < 12) g_zk[(size_t)b * 12 + lane] =
                    (lane < 6) ? pick6(z1, lane) : pick6(znew, lane - 6);
                if (lane == 31) g_ld[b] = ldb[si] - ssum;
            }

            // step 1 (U-factored, paired W3)
            float2 accv[3][6];
#pragma unroll
            for (int u = 0; u < 3; u++)
#pragma unroll
                for (int i = 0; i < 6; i++) accv[u][i] = make_float2(0.f, 0.f);
#pragma unroll
            for (int j = 0; j < 6; j++) {
                float2 gj[3];
#pragma unroll
                for (int u = 0; u < 3; u++)
                    gj[u] = make_float2(Vw[(2 * u) * 12 + j], Vw[(2 * u + 1) * 12 + j]);
                float fj = fac[j];
#pragma unroll
                for (int i = 0; i < 6; i++) {
                    float2 wp = w3pl[j * 192 + 32 * i];
                    float U = fmaf(fj, wp.y, wp.x);
                    float2 U2 = make_float2(U, U);
#pragma unroll
                    for (int u = 0; u < 3; u++) accv[u][i] = ffma2(gj[u], U2, accv[u][i]);
                }
            }

            // compact m2-active cols into 32B packets
            int pre = 0;
#pragma unroll
            for (int i = 0; i < 6; i++) pre += __popc(mm2[i]);
            bool hasov = (pre > CAP2);
            unsigned ovm[6];
            int base2 = 0;
#pragma unroll
            for (int i = 0; i < 6; i++) {
                unsigned m = mm2[i], keep = m;
                if (hasov) {
                    int pc = __popc(m);
                    int ovc = base2 + pc - CAP2;
                    if (ovc > 0) {
                        if (ovc > pc) ovc = pc;
                        for (int t = 0; t < ovc; t++) keep &= ~(0x80000000u >> __clz(keep));
                    }
                }
                ovm[i] = m ^ keep;
                if ((keep >> lane) & 1u) {
                    int pos = base2 + __popc(keep & lt);
                    int jjoff = (lane + 32 * i) * 193;
                    pw4[pos * 2 + 0] = make_float4(accv[0][i].x, accv[0][i].y, accv[1][i].x, accv[1][i].y);
                    pw4[pos * 2 + 1] = make_float4(accv[2][i].x, accv[2][i].y, __int_as_float(jjoff), 0.f);
                }
                base2 += __popc(keep);
            }
            int cnt2 = base2;
            if ((cnt2 & 1) && lane == 0) {
                pw4[cnt2 * 2 + 0] = make_float4(0.f, 0.f, 0.f, 0.f);
                pw4[cnt2 * 2 + 1] = make_float4(0.f, 0.f, __int_as_float(0), 0.f);
            }
            cnt2 += (cnt2 & 1);
            __syncwarp();

            // main loop: dense output cols lane+32i
            float2 a12[3][6];
#pragma unroll
            for (int u = 0; u < 3; u++)
#pragma unroll
                for (int i = 0; i < 6; i++) a12[u][i] = make_float2(0.f, 0.f);
            for (int c = 0; c < cnt2; c += 2) {
                float4 e0 = pw4[c * 2 + 0], e1 = pw4[c * 2 + 1];
                float4 f0 = pw4[c * 2 + 2], f1 = pw4[c * 2 + 3];
                const float* gp0 = w2rb + __float_as_int(e1.z);
                const float* gp1 = w2rb + __float_as_int(f1.z);
                float2 gA01 = make_float2(e0.x, e0.y);
                float2 gA23 = make_float2(e0.z, e0.w);
                float2 gA45 = make_float2(e1.x, e1.y);
                float2 gB01 = make_float2(f0.x, f0.y);
                float2 gB23 = make_float2(f0.z, f0.w);
                float2 gB45 = make_float2(f1.x, f1.y);
#pragma unroll
                for (int i = 0; i < 6; i++) {
                    float wv0 = gp0[32 * i], wv1 = gp1[32 * i];
                    float2 wd0 = make_float2(wv0, wv0), wd1 = make_float2(wv1, wv1);
                    a12[0][i] = ffma2(gA01, wd0, a12[0][i]);
                    a12[1][i] = ffma2(gA23, wd0, a12[1][i]);
                    a12[2][i] = ffma2(gA45, wd0, a12[2][i]);
                    a12[0][i] = ffma2(gB01, wd1, a12[0][i]);
                    a12[1][i] = ffma2(gB23, wd1, a12[1][i]);
                    a12[2][i] = ffma2(gB45, wd1, a12[2][i]);
                }
            }

            // overflow fallback (exact, rare ~1%): recompute g for dropped cols
            if (hasov) {
#pragma unroll
                for (int i = 0; i < 6; i++) {
                    unsigned ov = ovm[i];
                    while (ov) {
                        int src = __ffs(ov) - 1; ov &= ov - 1;
                        int jj = src + 32 * i;
                        float gg[6];
#pragma unroll
                        for (int v = 0; v < 6; v++) gg[v] = 0.f;
#pragma unroll
                        for (int j = 0; j < 6; j++) {
                            float2 wp = w3pb[j * 192 + jj];
                            float U = fmaf(fac[j], wp.y, wp.x);
#pragma unroll
                            for (int v = 0; v < 6; v++) gg[v] = fmaf(Vw[v * 12 + j], U, gg[v]);
                        }
                        float2 g01 = make_float2(gg[0], gg[1]);
                        float2 g23 = make_float2(gg[2], gg[3]);
                        float2 g45 = make_float2(gg[4], gg[5]);
                        const float* gp = w2rb + jj * 193;
#pragma unroll
                        for (int ii = 0; ii < 6; ii++) {
                            float wv = gp[32 * ii];
                            float2 wd = make_float2(wv, wv);
                            a12[0][ii] = ffma2(g01, wd, a12[0][ii]);
                            a12[1][ii] = ffma2(g23, wd, a12[1][ii]);
                            a12[2][ii] = ffma2(g45, wd, a12[2][ii]);
                        }
                    }
                }
            }

            // mask (mm1) then fold through W1t
            float2 pz2[3][6];
#pragma unroll
            for (int u = 0; u < 3; u++)
#pragma unroll
                for (int j = 0; j < 6; j++) pz2[u][j] = make_float2(0.f, 0.f);
#pragma unroll
            for (int i = 0; i < 6; i++) {
                float mi = ((mm1[i] >> lane) & 1u) ? 1.f : 0.f;
                float2 md = make_float2(mi, mi);
                float2 am0 = fmul2(a12[0][i], md);
                float2 am1 = fmul2(a12[1][i], md);
                float2 am2 = fmul2(a12[2][i], md);
#pragma unroll
                for (int j = 0; j < 6; j++) {
                    float wv = w1tl[j * 192 + 32 * i];
                    float2 wd = make_float2(wv, wv);
                    pz2[0][j] = ffma2(am0, wd, pz2[0][j]);
                    pz2[1][j] = ffma2(am1, wd, pz2[1][j]);
                    pz2[2][j] = ffma2(am2, wd, pz2[2][j]);
                }
            }

            // butterfly reduce
#pragma unroll
            for (int u = 0; u < 3; u++)
#pragma unroll
                for (int j = 0; j < 6; j++) {
                    F2U u2; u2.f = pz2[u][j];
#pragma unroll
                    for (int off = 16; off > 0; off >>= 1) {
                        F2U o2; o2.u = __shfl_xor_sync(0xffffffffu, u2.u, off);
                        u2.f = fadd2(u2.f, o2.f);
                    }
                    pz2[u][j] = u2.f;
                }

            // parallel write: lane j < 6 writes column j
            if (lane < 6) {
                int j = lane;
                float esj = pick6(es, j);
                float* vo = g_V + (size_t)b * 72;
#pragma unroll
                for (int u = 0; u < 3; u++) {
                    float2 pzv = pick6f2(pz2[u], j);
                    vo[(2 * u) * 12 + j]         = Vw[(2 * u) * 12 + 6 + j] + pzv.x;
                    vo[(2 * u) * 12 + 6 + j]     = Vw[(2 * u) * 12 + j] * esj;
                    vo[(2 * u + 1) * 12 + j]     = Vw[(2 * u + 1) * 12 + 6 + j] + pzv.y;
                    vo[(2 * u + 1) * 12 + 6 + j] = Vw[(2 * u + 1) * 12 + j] * esj;
                }
            }
        }
    }
}

// ---------------- deterministic Frobenius-norm reduction ----------------
__global__ void k_ssq_part() {
    float s = 0.f;
    for (int i = blockIdx.x * blockDim.x + threadIdx.x; i < B * 72; i += gridDim.x * blockDim.x) {
        float v = g_V[i]; s += v * v;
    }
    __shared__ float red[256];
    red[threadIdx.x] = s; __syncthreads();
    for (int o = 128; o > 0; o >>= 1) {
        if (threadIdx.x < o) red[threadIdx.x] += red[threadIdx.x + o];
        __syncthreads();
    }
    if (threadIdx.x == 0) g_part[blockIdx.x] = red[0];
}
__global__ void k_ssq_final() {
    __shared__ float red[256];
    red[threadIdx.x] = g_part[threadIdx.x]; __syncthreads();
    for (int o = 128; o > 0; o >>= 1) {
        if (threadIdx.x < o) red[threadIdx.x] += red[threadIdx.x + o];
        __syncthreads();
    }
    if (threadIdx.x == 0) g_ssq = red[0];
}

// ---------------- KL + log_prob: 4 lanes per sample (m-split) ----------------
#define LIX(r, c) ((r) * ((r) + 1) / 2 + (c))
#define ASTR 148

__global__ void __launch_bounds__(128) k_kl(
    const float* __restrict__ Wsym, const float* __restrict__ lvd,
    float* __restrict__ out)
{
    __shared__ float As[NB * ASTR];
    int tid = threadIdx.x;
    for (int i = tid; i < NB * 144; i += 128) {
        int m = i / 144; int rc = i % 144; int r = rc / 12; int c = rc % 12;
        As[m * ASTR + rc] = Wsym[m * 144 + r * 12 + c] - Wsym[m * 144 + c * 12 + r];
    }
    __syncthreads();

    int gid = blockIdx.x * 128 + tid;
    int s   = gid >> 2;
    int sub = gid & 3;
    if (s >= B) return;

    float zr[12]; float zz = 0.f;
#pragma unroll
    for (int i = 0; i < 12; i++) { zr[i] = g_zk[(size_t)s * 12 + i]; zz += zr[i] * zr[i]; }
    float2 zr2[6];
#pragma unroll
    for (int p = 0; p < 6; p++) zr2[p] = make_float2(zr[2 * p], zr[2 * p + 1]);

    float scale = rsqrtf(g_ssq);
    float Jp[6][12];
#pragma unroll
    for (int v = 0; v < 6; v++)
#pragma unroll
        for (int i = 0; i < 12; i++) Jp[v][i] = g_V[(size_t)s * 72 + v * 12 + i] * scale;

    float Sql[78];
#pragma unroll
    for (int i = 0; i < 78; i++) Sql[i] = 0.f;
    float trq = 0.f, trpq = 0.f;

    for (int m = sub; m < NB; m += 4) {
        const float* Am = As + m * ASTR;
        float Jq[12];
#pragma unroll
        for (int jj = 0; jj < 12; jj++) {
            float2 a2 = make_float2(0.f, 0.f);
#pragma unroll
            for (int ip = 0; ip < 6; ip++)
                a2 = ffma2(*(const float2*)(Am + jj * 12 + 2 * ip), zr2[ip], a2);
            float a = a2.x + a2.y;
            Jq[jj] = a; trq = fmaf(a, a, trq);
        }
#pragma unroll
        for (int n = 0; n < 12; n++)
#pragma unroll
            for (int mm = 0; mm <= n; mm++) Sql[LIX(n, mm)] = fmaf(Jq[n], Jq[mm], Sql[LIX(n, mm)]);
#pragma unroll
        for (int v = 0; v < 6; v++) {
            float2 d2 = make_float2(0.f, 0.f);
#pragma unroll
            for (int ip = 0; ip < 6; ip++)
                d2 = ffma2(make_float2(Jp[v][2 * ip], Jp[v][2 * ip + 1]),
                           make_float2(Jq[2 * ip], Jq[2 * ip + 1]), d2);
            float d = d2.x + d2.y;
            trpq = fmaf(d, d, trpq);
        }
    }

#pragma unroll
    for (int i = 0; i < 78; i += 2) {
        F2U u; u.f = make_float2(Sql[i], Sql[i + 1]);
        F2U o1; o1.u = __shfl_xor_sync(0xffffffffu, u.u, 1); u.f = fadd2(u.f, o1.f);
        F2U o2; o2.u = __shfl_xor_sync(0xffffffffu, u.u, 2); u.f = fadd2(u.f, o2.f);
        Sql[i] = u.f.x; Sql[i + 1] = u.f.y;
    }
    {
        F2U u; u.f = make_float2(trq, trpq);
        F2U o1; o1.u = __shfl_xor_sync(0xffffffffu, u.u, 1); u.f = fadd2(u.f, o1.f);
        F2U o2; o2.u = __shfl_xor_sync(0xffffffffu, u.u, 2); u.f = fadd2(u.f, o2.f);
        trq = u.f.x; trpq = u.f.y;
    }
    if (sub != 0) return;

    out[s] = g_ld[s] - 6.f * 1.8378770664093453f - 0.5f * zz;

    float Ml[21];
#pragma unroll
    for (int a = 0; a < 6; a++)
#pragma unroll
        for (int c = 0; c <= a; c++) {
            float acc = 0.f;
#pragma unroll
            for (int i = 0; i < 12; i++) acc = fmaf(Jp[a][i], Jp[c][i], acc);
            Ml[LIX(a, c)] = acc;
        }
#pragma unroll
    for (int d = 0; d < 6; d++) Ml[LIX(d, d)] += 1e-3f;
    float dm = 0.f;
#pragma unroll
    for (int d = 0; d < 6; d++) dm += Ml[LIX(d, d)];
    float normM = fmaxf(dm * (1.f / 6.f), 1e-6f);
#pragma unroll
    for (int d = 0; d < 6; d++) Ml[LIX(d, d)] += 1e-3f * normM;

    float D[12];
#pragma unroll
    for (int i = 0; i < 12; i++) D[i] = expf(-lvd[i]);
#pragma unroll
    for (int d = 0; d < 12; d++) Sql[LIX(d, d)] += D[d];
    float dh = 0.f;
#pragma unroll
    for (int d = 0; d < 12; d++) dh += Sql[LIX(d, d)];
    float normH = fmaxf(dh * (1.f / 12.f), 1e-6f);
#pragma unroll
    for (int d = 0; d < 12; d++) Sql[LIX(d, d)] += 1e-3f * normH;

    float Db[12], sumDb = 0.f;
#pragma unroll
    for (int i = 0; i < 12; i++) { Db[i] = D[i] + 1e-3f * normH; sumDb += Db[i]; }

    float trp = 0.f;
#pragma unroll
    for (int v = 0; v < 6; v++)
#pragma unroll
        for (int i = 0; i < 12; i++) trp = fmaf(Jp[v][i] * Jp[v][i], Db[i], trp);

    float trace = (1e-3f + 1e-3f * normM) * (sumDb + trq) + trp + trpq;

    float ldM = 0.f;
#pragma unroll
    for (int c = 0; c < 6; c++) {
        float d = Ml[LIX(c, c)];
#pragma unroll
        for (int kk = 0; kk < c; kk++) d -= Ml[LIX(c, kk)] * Ml[LIX(c, kk)];
        d = sqrtf(d); ldM += 2.f * logf(d);
        float inv = 1.f / d;
#pragma unroll
        for (int r = c + 1; r < 6; r++) {
            float a = Ml[LIX(r, c)];
#pragma unroll
            for (int kk = 0; kk < c; kk++) a -= Ml[LIX(r, kk)] * Ml[LIX(c, kk)];
            Ml[LIX(r, c)] = a * inv;
        }
    }
    float ldH = 0.f;
#pragma unroll
    for (int c = 0; c < 12; c++) {
        float d = Sql[LIX(c, c)];
#pragma unroll
        for (int kk = 0; kk < c; kk++) d -= Sql[LIX(c, kk)] * Sql[LIX(c, kk)];
        d = sqrtf(d); ldH += 2.f * logf(d);
        float inv = 1.f / d;
#pragma unroll
        for (int r = c + 1; r < 12; r++) {
            float a = Sql[LIX(r, c)];
#pragma unroll
            for (int kk = 0; kk < c; kk++) a -= Sql[LIX(r, kk)] * Sql[LIX(c, kk)];
            Sql[LIX(r, c)] = a * inv;
        }
    }

    float logdet_p = ldM + 6.f * (-6.907755278982137f);
    out[B + s] = 0.5f * (trace - logdet_p - ldH - 12.f);
}

// ---------------- host launcher ----------------
extern "C" void kernel_launch(void* const* d_in, const int* in_sizes, int n_in,
                              void* d_out, int out_size) {
    const float* y    = (const float*)d_in[0];
    const float* Jp   = (const float*)d_in[1];
    const float* W1   = (const float*)d_in[2];
    const float* b1   = (const float*)d_in[3];
    const float* W2   = (const float*)d_in[4];
    const float* b2   = (const float*)d_in[5];
    const float* W3   = (const float*)d_in[6];
    const float* b3   = (const float*)d_in[7];
    const float* Wsym = (const float*)d_in[8];
    const float* lvd  = (const float*)d_in[9];
    float* out = (float*)d_out;

    const int SMEM_F = (OFF_WARP + 16 * WSTRIDE) * 4;  // 231,744 B
    cudaFuncSetAttribute(k_fused, cudaFuncAttributeMaxDynamicSharedMemorySize, SMEM_F);

    k_init<<<256, 256>>>(Jp);
    k_fused<<<152, 512, SMEM_F>>>(y, W1, b1, W2, b2, W3, b3);
    k_ssq_part<<<256, 256>>>();
    k_ssq_final<<<1, 256>>>();
    k_kl<<<(B * 4) / 128, 128>>>(Wsym, lvd, out);
}

// round 16
// speedup vs baseline: 1.0038x; 1.0010x over previous
#include <cuda_runtime.h>
#include <math.h>

#define B      16384
#define DIN    12
#define HID    192
#define LAYERS 24
#define NB     66
#define CAP2   112

// ---------------- scratch ----------------
__device__ float g_zk[B * DIN];       // final z (k=0) for k_kl
__device__ float g_V [B * 72];
__device__ float g_ld[B];
__device__ float g_part[256];
__device__ float g_ssq;

// ---------------- f32x2 packed ops ----------------
union F2U { float2 f; unsigned long long u; };
__device__ __forceinline__ float2 ffma2(float2 a, float2 b, float2 c) {
    F2U A, Bv, C, D; A.f = a; Bv.f = b; C.f = c;
    asm("fma.rn.f32x2 %0,%1,%2,%3;" : "=l"(D.u) : "l"(A.u), "l"(Bv.u), "l"(C.u));
    return D.f;
}
__device__ __forceinline__ float2 fmul2(float2 a, float2 b) {
    F2U A, Bv, D; A.f = a; Bv.f = b;
    asm("mul.rn.f32x2 %0,%1,%2;" : "=l"(D.u) : "l"(A.u), "l"(Bv.u));
    return D.f;
}
__device__ __forceinline__ float2 fadd2(float2 a, float2 b) {
    F2U A, Bv, D; A.f = a; Bv.f = b;
    asm("add.rn.f32x2 %0,%1,%2;" : "=l"(D.u) : "l"(A.u), "l"(Bv.u));
    return D.f;
}

__device__ __forceinline__ float pick6(const float a[6], int i) {
    float r = a[0];
    if (i == 1) r = a[1];
    if (i == 2) r = a[2];
    if (i == 3) r = a[3];
    if (i == 4) r = a[4];
    if (i == 5) r = a[5];
    return r;
}
__device__ __forceinline__ float2 pick6f2(const float2 a[6], int i) {
    float2 r = a[0];
    if (i == 1) r = a[1];
    if (i == 2) r = a[2];
    if (i == 3) r = a[3];
    if (i == 4) r = a[4];
    if (i == 5) r = a[5];
    return r;
}

// ---------------- init (g_V only) ----------------
__global__ void k_init(const float* __restrict__ Jp) {
    int i0 = blockIdx.x * blockDim.x + threadIdx.x;
    int st = gridDim.x * blockDim.x;
    for (int i = i0; i < B * 72; i += st) g_V[i] = Jp[i];
}

// smem float offsets
#define OFF_W2R  0        // [192][193]: W2R[a*193+b] = W2[a][b]
#define OFF_W3   37056    // paired: float2[6*192]: (W3[2j][c], W3[2j+1][c])
#define OFF_W1T  39360    // [6][192]: W1t[j*192+r] = W1[r][j]
#define OFF_B1   40512
#define OFF_B2   40704
#define OFF_B3   40896    // 16
#define OFF_WARP 40912
#define WSTRIDE  1064
// per-warp floats: [0,896) entries (inv list float2 / vjp packets 2xfloat4, CAP2=112),
//                  [896,968) Vw, [968,1052) zbuf (7 samples x 12), [1052,1060) ldb

// ---------------- persistent fused inverse + VJP over all layers ----------------
__global__ void __launch_bounds__(512) k_fused(
    const float* __restrict__ y,
    const float* __restrict__ W1, const float* __restrict__ b1,
    const float* __restrict__ W2, const float* __restrict__ b2,
    const float* __restrict__ W3, const float* __restrict__ b3)
{
    extern __shared__ float sm[];
    int tid = threadIdx.x;
    int lane = tid & 31, wip = tid >> 5;

    float*  wb   = sm + OFF_WARP + wip * WSTRIDE;
    float2* pw   = (float2*)wb;
    float4* pw4  = (float4*)wb;
    float*  Vw   = wb + 896;
    float*  zbuf = wb + 968;
    float*  ldb  = wb + 1052;
    unsigned lt = (1u << lane) - 1u;

    const float*  w2rl = sm + OFF_W2R + lane * 193;
    const float*  w2rb = sm + OFF_W2R + lane;
    const float2* w3pl = ((const float2*)(sm + OFF_W3)) + lane;
    const float2* w3pb = (const float2*)(sm + OFF_W3);
    const float*  w1tl = sm + OFF_W1T + lane;
    const float*  b1l  = sm + OFF_B1 + lane;
    const float*  b2l  = sm + OFF_B2 + lane;
    const float*  b3s  = sm + OFF_B3;

    int w  = (blockIdx.x * 512 + tid) >> 5;
    int nw = gridDim.x * 16;

    // init per-warp z buffers (y) and logdet accumulators
#pragma unroll
    for (int si = 0; si < 7; si++) {
        int b = w + si * nw;
        if (b < B && lane < 12) zbuf[si * 12 + lane] = y[(size_t)b * 12 + lane];
    }
    if (lane < 7) ldb[lane] = 0.f;

    for (int k = LAYERS - 1; k >= 0; k--) {
        __syncthreads();   // all warps done reading previous layer's weights
        // ---- stage layer-k weights ----
        {
            const float* W2k = W2 + (size_t)k * HID * HID;
            const float* W3k = W3 + (size_t)k * 12 * HID;
            const float* W1k = W1 + (size_t)k * HID * 6;
            const float* b1k = b1 + (size_t)k * HID;
            const float* b2k = b2 + (size_t)k * HID;
            const float* b3k = b3 + (size_t)k * 12;
            for (int i = tid; i < HID * HID; i += 512) {
                int a = i / HID, bb = i % HID;
                sm[OFF_W2R + a * 193 + bb] = W2k[i];
            }
            float2* w3p = (float2*)(sm + OFF_W3);
            for (int i = tid; i < 6 * HID; i += 512) {
                int j = i / HID, col = i % HID;
                w3p[j * 192 + col] = make_float2(W3k[(2 * j) * HID + col],
                                                 W3k[(2 * j + 1) * HID + col]);
            }
            for (int i = tid; i < HID * 6; i += 512) {
                int r = i / 6, j = i % 6;
                sm[OFF_W1T + j * 192 + r] = W1k[i];
            }
            for (int i = tid; i < HID; i += 512) { sm[OFF_B1 + i] = b1k[i]; sm[OFF_B2 + i] = b2k[i]; }
            if (tid < 12) sm[OFF_B3 + tid] = b3k[tid];
        }
        __syncthreads();

        // ---- process this warp's samples ----
#pragma unroll 1
        for (int si = 0; si < 7; si++) {
            int b = w + si * nw;
            if (b >= B) continue;
            float* zs = zbuf + si * 12;

            __syncwarp();
            // hoisted Vw load (hidden behind inverse phase)
            {
                const float* vp = g_V + (size_t)b * 72;
                Vw[lane]      = vp[lane];
                Vw[lane + 32] = vp[lane + 32];
                if (lane < 8) Vw[lane + 64] = vp[lane + 64];
            }
            float z1[6], z2[6];
#pragma unroll
            for (int j = 0; j < 6; j++) { z1[j] = zs[6 + j]; z2[j] = zs[j]; }

            // ===== INVERSE =====
            unsigned mm1[6];
            int base = 0;
#pragma unroll
            for (int i = 0; i < 6; i++) {
                float a = b1l[32 * i];
#pragma unroll
                for (int j = 0; j < 6; j++) a = fmaf(w1tl[j * 192 + 32 * i], z1[j], a);
                unsigned m = __ballot_sync(0xffffffffu, a > 0.f);
                mm1[i] = m;
                if ((m >> lane) & 1u) {
                    int pos = base + __popc(m & lt);
                    pw[pos] = make_float2(a, __int_as_float(lane + 32 * i));
                }
                base += __popc(m);
            }
            int cnt1 = base;
            int pad1 = (-cnt1) & 3;
            if (lane < pad1) pw[cnt1 + lane] = make_float2(0.f, __int_as_float(0));
            int cnt1r = cnt1 + pad1;
            __syncwarp();

            // L2
            float2 hacc[6];
#pragma unroll
            for (int i = 0; i < 6; i++) hacc[i] = make_float2(b2l[32 * i], 0.f);
            for (int c = 0; c < cnt1r; c += 4) {
                float4 L0 = pw4[c >> 1], L1 = pw4[(c >> 1) + 1];
                const float* rp0 = w2rl + __float_as_int(L0.y);
                const float* rp1 = w2rl + __float_as_int(L0.w);
                const float* rp2 = w2rl + __float_as_int(L1.y);
                const float* rp3 = w2rl + __float_as_int(L1.w);
                float2 h01 = make_float2(L0.x, L0.z);
                float2 h23 = make_float2(L1.x, L1.z);
#pragma unroll
                for (int i = 0; i < 6; i++) {
                    hacc[i] = ffma2(make_float2(rp0[6176 * i], rp1[6176 * i]), h01, hacc[i]);
                    hacc[i] = ffma2(make_float2(rp2[6176 * i], rp3[6176 * i]), h23, hacc[i]);
                }
            }
            unsigned mm2[6];
            float h2a[6];
#pragma unroll
            for (int i = 0; i < 6; i++) {
                float hv = hacc[i].x + hacc[i].y;
                mm2[i] = __ballot_sync(0xffffffffu, hv > 0.f);
                h2a[i] = fmaxf(hv, 0.f);
            }

            // L3 via paired W3 (LDS.64)
            float2 shsr[6];
#pragma unroll
            for (int oj = 0; oj < 6; oj++) {
                float2 acc = make_float2(0.f, 0.f);
#pragma unroll
                for (int i = 0; i < 6; i++) {
                    float hv = h2a[i];
                    acc = ffma2(w3pl[oj * 192 + 32 * i], make_float2(hv, hv), acc);
                }
                F2U u; u.f = acc;
#pragma unroll
                for (int off = 16; off > 0; off >>= 1) {
                    F2U o2; o2.u = __shfl_xor_sync(0xffffffffu, u.u, off);
                    u.f = fadd2(u.f, o2.f);
                }
                shsr[oj] = u.f;
            }

            // epilogue
            float ssum = 0.f, znew[6], es[6], fac[6];
#pragma unroll
            for (int j = 0; j < 6; j++) {
                float sh = shsr[j].x + b3s[2 * j];
                float sr = shsr[j].y + b3s[2 * j + 1];
                float s  = 2.f * tanhf(0.5f * sr);
                ssum += s;
                float em = expf(-s);
                znew[j] = (z2[j] - sh) * em;
                es[j]   = expf(s);
                float t2 = 0.5f * s;
                fac[j]  = znew[j] * es[j] * (1.f - t2 * t2);
            }

            // ===== VJP =====
            __syncwarp();
            // commit new z (smem for next layer; global only at k==0)
            if (k > 0) {
                if (lane < 12) zs[lane] = (lane < 6) ? pick6(z1, lane) : pick6(znew, lane - 6);
                if (lane == 31) ldb[si] -= ssum;
            } else {
                if (lane < 12) g_zk[(size_t)b * 12 + lane] =
                    (lane < 6) ? pick6(z1, lane) : pick6(znew, lane - 6);
                if (lane == 31) g_ld[b] = ldb[si] - ssum;
            }

            // step 1 (U-factored, paired W3)
            float2 accv[3][6];
#pragma unroll
            for (int u = 0; u < 3; u++)
#pragma unroll
                for (int i = 0; i < 6; i++) accv[u][i] = make_float2(0.f, 0.f);
#pragma unroll
            for (int j = 0; j < 6; j++) {
                float2 gj[3];
#pragma unroll
                for (int u = 0; u < 3; u++)
                    gj[u] = make_float2(Vw[(2 * u) * 12 + j], Vw[(2 * u + 1) * 12 + j]);
                float fj = fac[j];
#pragma unroll
                for (int i = 0; i < 6; i++) {
                    float2 wp = w3pl[j * 192 + 32 * i];
                    float U = fmaf(fj, wp.y, wp.x);
                    float2 U2 = make_float2(U, U);
#pragma unroll
                    for (int u = 0; u < 3; u++) accv[u][i] = ffma2(gj[u], U2, accv[u][i]);
                }
            }

            // compact m2-active cols into 32B packets
            int pre = 0;
#pragma unroll
            for (int i = 0; i < 6; i++) pre += __popc(mm2[i]);
            bool hasov = (pre > CAP2);
            unsigned ovm[6];
            int base2 = 0;
#pragma unroll
            for (int i = 0; i < 6; i++) {
                unsigned m = mm2[i], keep = m;
                if (hasov) {
                    int pc = __popc(m);
                    int ovc = base2 + pc - CAP2;
                    if (ovc > 0) {
                        if (ovc > pc) ovc = pc;
                        for (int t = 0; t < ovc; t++) keep &= ~(0x80000000u >> __clz(keep));
                    }
                }
                ovm[i] = m ^ keep;
                if ((keep >> lane) & 1u) {
                    int pos = base2 + __popc(keep & lt);
                    int jjoff = (lane + 32 * i) * 193;
                    pw4[pos * 2 + 0] = make_float4(accv[0][i].x, accv[0][i].y, accv[1][i].x, accv[1][i].y);
                    pw4[pos * 2 + 1] = make_float4(accv[2][i].x, accv[2][i].y, __int_as_float(jjoff), 0.f);
                }
                base2 += __popc(keep);
            }
            int cnt2 = base2;
            if ((cnt2 & 1) && lane == 0) {
                pw4[cnt2 * 2 + 0] = make_float4(0.f, 0.f, 0.f, 0.f);
                pw4[cnt2 * 2 + 1] = make_float4(0.f, 0.f, __int_as_float(0), 0.f);
            }
            cnt2 += (cnt2 & 1);
            __syncwarp();

            // main loop: dense output cols lane+32i
            float2 a12[3][6];
#pragma unroll
            for (int u = 0; u < 3; u++)
#pragma unroll
                for (int i = 0; i < 6; i++) a12[u][i] = make_float2(0.f, 0.f);
            for (int c = 0; c < cnt2; c += 2) {
                float4 e0 = pw4[c * 2 + 0], e1 = pw4[c * 2 + 1];
                float4 f0 = pw4[c * 2 + 2], f1 = pw4[c * 2 + 3];
                const float* gp0 = w2rb + __float_as_int(e1.z);
                const float* gp1 = w2rb + __float_as_int(f1.z);
                float2 gA01 = make_float2(e0.x, e0.y);
                float2 gA23 = make_float2(e0.z, e0.w);
                float2 gA45 = make_float2(e1.x, e1.y);
                float2 gB01 = make_float2(f0.x, f0.y);
                float2 gB23 = make_float2(f0.z, f0.w);
                float2 gB45 = make_float2(f1.x, f1.y);
#pragma unroll
                for (int i = 0; i < 6; i++) {
                    float wv0 = gp0[32 * i], wv1 = gp1[32 * i];
                    float2 wd0 = make_float2(wv0, wv0), wd1 = make_float2(wv1, wv1);
                    a12[0][i] = ffma2(gA01, wd0, a12[0][i]);
                    a12[1][i] = ffma2(gA23, wd0, a12[1][i]);
                    a12[2][i] = ffma2(gA45, wd0, a12[2][i]);
                    a12[0][i] = ffma2(gB01, wd1, a12[0][i]);
                    a12[1][i] = ffma2(gB23, wd1, a12[1][i]);
                    a12[2][i] = ffma2(gB45, wd1, a12[2][i]);
                }
            }

            // overflow fallback (exact, rare ~1%): recompute g for dropped cols
            if (hasov) {
#pragma unroll
                for (int i = 0; i < 6; i++) {
                    unsigned ov = ovm[i];
                    while (ov) {
                        int src = __ffs(ov) - 1; ov &= ov - 1;
                        int jj = src + 32 * i;
                        float gg[6];
#pragma unroll
                        for (int v = 0; v < 6; v++) gg[v] = 0.f;
#pragma unroll
                        for (int j = 0; j < 6; j++) {
                            float2 wp = w3pb[j * 192 + jj];
                            float U = fmaf(fac[j], wp.y, wp.x);
#pragma unroll
                            for (int v = 0; v < 6; v++) gg[v] = fmaf(Vw[v * 12 + j], U, gg[v]);
                        }
                        float2 g01 = make_float2(gg[0], gg[1]);
                        float2 g23 = make_float2(gg[2], gg[3]);
                        float2 g45 = make_float2(gg[4], gg[5]);
                        const float* gp = w2rb + jj * 193;
#pragma unroll
                        for (int ii = 0; ii < 6; ii++) {
                            float wv = gp[32 * ii];
                            float2 wd = make_float2(wv, wv);
                            a12[0][ii] = ffma2(g01, wd, a12[0][ii]);
                            a12[1][ii] = ffma2(g23, wd, a12[1][ii]);
                            a12[2][ii] = ffma2(g45, wd, a12[2][ii]);
                        }
                    }
                }
            }

            // mask (mm1) then fold through W1t
            float2 pz2[3][6];
#pragma unroll
            for (int u = 0; u < 3; u++)
#pragma unroll
                for (int j = 0; j < 6; j++) pz2[u][j] = make_float2(0.f, 0.f);
#pragma unroll
            for (int i = 0; i < 6; i++) {
                float mi = ((mm1[i] >> lane) & 1u) ? 1.f : 0.f;
                float2 md = make_float2(mi, mi);
                float2 am0 = fmul2(a12[0][i], md);
                float2 am1 = fmul2(a12[1][i], md);
                float2 am2 = fmul2(a12[2][i], md);
#pragma unroll
                for (int j = 0; j < 6; j++) {
                    float wv = w1tl[j * 192 + 32 * i];
                    float2 wd = make_float2(wv, wv);
                    pz2[0][j] = ffma2(am0, wd, pz2[0][j]);
                    pz2[1][j] = ffma2(am1, wd, pz2[1][j]);
                    pz2[2][j] = ffma2(am2, wd, pz2[2][j]);
                }
            }

            // butterfly reduce
#pragma unroll
            for (int u = 0; u < 3; u++)
#pragma unroll
                for (int j = 0; j < 6; j++) {
                    F2U u2; u2.f = pz2[u][j];
#pragma unroll
                    for (int off = 16; off > 0; off >>= 1) {
                        F2U o2; o2.u = __shfl_xor_sync(0xffffffffu, u2.u, off);
                        u2.f = fadd2(u2.f, o2.f);
                    }
                    pz2[u][j] = u2.f;
                }

            // parallel write: lane j < 6 writes column j
            if (lane < 6) {
                int j = lane;
                float esj = pick6(es, j);
                float* vo = g_V + (size_t)b * 72;
#pragma unroll
                for (int u = 0; u < 3; u++) {
                    float2 pzv = pick6f2(pz2[u], j);
                    vo[(2 * u) * 12 + j]         = Vw[(2 * u) * 12 + 6 + j] + pzv.x;
                    vo[(2 * u) * 12 + 6 + j]     = Vw[(2 * u) * 12 + j] * esj;
                    vo[(2 * u + 1) * 12 + j]     = Vw[(2 * u + 1) * 12 + 6 + j] + pzv.y;
                    vo[(2 * u + 1) * 12 + 6 + j] = Vw[(2 * u + 1) * 12 + j] * esj;
                }
            }
        }
    }
}

// ---------------- deterministic Frobenius-norm reduction ----------------
__global__ void k_ssq_part() {
    float s = 0.f;
    for (int i = blockIdx.x * blockDim.x + threadIdx.x; i < B * 72; i += gridDim.x * blockDim.x) {
        float v = g_V[i]; s += v * v;
    }
    __shared__ float red[256];
    red[threadIdx.x] = s; __syncthreads();
    for (int o = 128; o > 0; o >>= 1) {
        if (threadIdx.x < o) red[threadIdx.x] += red[threadIdx.x + o];
        __syncthreads();
    }
    if (threadIdx.x == 0) g_part[blockIdx.x] = red[0];
}
__global__ void k_ssq_final() {
    __shared__ float red[256];
    red[threadIdx.x] = g_part[threadIdx.x]; __syncthreads();
    for (int o = 128; o > 0; o >>= 1) {
        if (threadIdx.x < o) red[threadIdx.x] += red[threadIdx.x + o];
        __syncthreads();
    }
    if (threadIdx.x == 0) g_ssq = red[0];
}

// ---------------- KL + log_prob: 4 lanes per sample (m-split) ----------------
#define LIX(r, c) ((r) * ((r) + 1) / 2 + (c))
#define ASTR 148

__global__ void __launch_bounds__(128) k_kl(
    const float* __restrict__ Wsym, const float* __restrict__ lvd,
    float* __restrict__ out)
{
    __shared__ float As[NB * ASTR];
    int tid = threadIdx.x;
    for (int i = tid; i < NB * 144; i += 128) {
        int m = i / 144; int rc = i % 144; int r = rc / 12; int c = rc % 12;
        As[m * ASTR + rc] = Wsym[m * 144 + r * 12 + c] - Wsym[m * 144 + c * 12 + r];
    }
    __syncthreads();

    int gid = blockIdx.x * 128 + tid;
    int s   = gid >> 2;
    int sub = gid & 3;
    if (s >= B) return;

    float zr[12]; float zz = 0.f;
#pragma unroll
    for (int i = 0; i < 12; i++) { zr[i] = g_zk[(size_t)s * 12 + i]; zz += zr[i] * zr[i]; }
    float2 zr2[6];
#pragma unroll
    for (int p = 0; p < 6; p++) zr2[p] = make_float2(zr[2 * p], zr[2 * p + 1]);

    float scale = rsqrtf(g_ssq);
    float Jp[6][12];
#pragma unroll
    for (int v = 0; v < 6; v++)
#pragma unroll
        for (int i = 0; i < 12; i++) Jp[v][i] = g_V[(size_t)s * 72 + v * 12 + i] * scale;

    float Sql[78];
#pragma unroll
    for (int i = 0; i < 78; i++) Sql[i] = 0.f;
    float trq = 0.f, trpq = 0.f;

    for (int m = sub; m < NB; m += 4) {
        const float* Am = As + m * ASTR;
        float Jq[12];
#pragma unroll
        for (int jj = 0; jj < 12; jj++) {
            float2 a2 = make_float2(0.f, 0.f);
#pragma unroll
            for (int ip = 0; ip < 6; ip++)
                a2 = ffma2(*(const float2*)(Am + jj * 12 + 2 * ip), zr2[ip], a2);
            float a = a2.x + a2.y;
            Jq[jj] = a; trq = fmaf(a, a, trq);
        }
#pragma unroll
        for (int n = 0; n < 12; n++)
#pragma unroll
            for (int mm = 0; mm <= n; mm++) Sql[LIX(n, mm)] = fmaf(Jq[n], Jq[mm], Sql[LIX(n, mm)]);
#pragma unroll
        for (int v = 0; v < 6; v++) {
            float2 d2 = make_float2(0.f, 0.f);
#pragma unroll
            for (int ip = 0; ip < 6; ip++)
                d2 = ffma2(make_float2(Jp[v][2 * ip], Jp[v][2 * ip + 1]),
                           make_float2(Jq[2 * ip], Jq[2 * ip + 1]), d2);
            float d = d2.x + d2.y;
            trpq = fmaf(d, d, trpq);
        }
    }

#pragma unroll
    for (int i = 0; i < 78; i += 2) {
        F2U u; u.f = make_float2(Sql[i], Sql[i + 1]);
        F2U o1; o1.u = __shfl_xor_sync(0xffffffffu, u.u, 1); u.f = fadd2(u.f, o1.f);
        F2U o2; o2.u = __shfl_xor_sync(0xffffffffu, u.u, 2); u.f = fadd2(u.f, o2.f);
        Sql[i] = u.f.x; Sql[i + 1] = u.f.y;
    }
    {
        F2U u; u.f = make_float2(trq, trpq);
        F2U o1; o1.u = __shfl_xor_sync(0xffffffffu, u.u, 1); u.f = fadd2(u.f, o1.f);
        F2U o2; o2.u = __shfl_xor_sync(0xffffffffu, u.u, 2); u.f = fadd2(u.f, o2.f);
        trq = u.f.x; trpq = u.f.y;
    }
    if (sub != 0) return;

    out[s] = g_ld[s] - 6.f * 1.8378770664093453f - 0.5f * zz;

    float Ml[21];
#pragma unroll
    for (int a = 0; a < 6; a++)
#pragma unroll
        for (int c = 0; c <= a; c++) {
            float acc = 0.f;
#pragma unroll
            for (int i = 0; i < 12; i++) acc = fmaf(Jp[a][i], Jp[c][i], acc);
            Ml[LIX(a, c)] = acc;
        }
#pragma unroll
    for (int d = 0; d < 6; d++) Ml[LIX(d, d)] += 1e-3f;
    float dm = 0.f;
#pragma unroll
    for (int d = 0; d < 6; d++) dm += Ml[LIX(d, d)];
    float normM = fmaxf(dm * (1.f / 6.f), 1e-6f);
#pragma unroll
    for (int d = 0; d < 6; d++) Ml[LIX(d, d)] += 1e-3f * normM;

    float D[12];
#pragma unroll
    for (int i = 0; i < 12; i++) D[i] = expf(-lvd[i]);
#pragma unroll
    for (int d = 0; d < 12; d++) Sql[LIX(d, d)] += D[d];
    float dh = 0.f;
#pragma unroll
    for (int d = 0; d < 12; d++) dh += Sql[LIX(d, d)];
    float normH = fmaxf(dh * (1.f / 12.f), 1e-6f);
#pragma unroll
    for (int d = 0; d < 12; d++) Sql[LIX(d, d)] += 1e-3f * normH;

    float Db[12], sumDb = 0.f;
#pragma unroll
    for (int i = 0; i < 12; i++) { Db[i] = D[i] + 1e-3f * normH; sumDb += Db[i]; }

    float trp = 0.f;
#pragma unroll
    for (int v = 0; v < 6; v++)
#pragma unroll
        for (int i = 0; i < 12; i++) trp = fmaf(Jp[v][i] * Jp[v][i], Db[i], trp);

    float trace = (1e-3f + 1e-3f * normM) * (sumDb + trq) + trp + trpq;

    float ldM = 0.f;
#pragma unroll
    for (int c = 0; c < 6; c++) {
        float d = Ml[LIX(c, c)];
#pragma unroll
        for (int kk = 0; kk < c; kk++) d -= Ml[LIX(c, kk)] * Ml[LIX(c, kk)];
        d = sqrtf(d); ldM += 2.f * logf(d);
        float inv = 1.f / d;
#pragma unroll
        for (int r = c + 1; r < 6; r++) {
            float a = Ml[LIX(r, c)];
#pragma unroll
            for (int kk = 0; kk < c; kk++) a -= Ml[LIX(r, kk)] * Ml[LIX(c, kk)];
            Ml[LIX(r, c)] = a * inv;
        }
    }
    float ldH = 0.f;
#pragma unroll
    for (int c = 0; c < 12; c++) {
        float d = Sql[LIX(c, c)];
#pragma unroll
        for (int kk = 0; kk < c; kk++) d -= Sql[LIX(c, kk)] * Sql[LIX(c, kk)];
        d = sqrtf(d); ldH += 2.f * logf(d);
        float inv = 1.f / d;
#pragma unroll
        for (int r = c + 1; r < 12; r++) {
            float a = Sql[LIX(r, c)];
#pragma unroll
            for (int kk = 0; kk < c; kk++) a -= Sql[LIX(r, kk)] * Sql[LIX(c, kk)];
            Sql[LIX(r, c)] = a * inv;
        }
    }

    float logdet_p = ldM + 6.f * (-6.907755278982137f);
    out[B + s] = 0.5f * (trace - logdet_p - ldH - 12.f);
}

// ---------------- host launcher ----------------
extern "C" void kernel_launch(void* const* d_in, const int* in_sizes, int n_in,
                              void* d_out, int out_size) {
    const float* y    = (const float*)d_in[0];
    const float* Jp   = (const float*)d_in[1];
    const float* W1   = (const float*)d_in[2];
    const float* b1   = (const float*)d_in[3];
    const float* W2   = (const float*)d_in[4];
    const float* b2   = (const float*)d_in[5];
    const float* W3   = (const float*)d_in[6];
    const float* b3   = (const float*)d_in[7];
    const float* Wsym = (const float*)d_in[8];
    const float* lvd  = (const float*)d_in[9];
    float* out = (float*)d_out;

    const int SMEM_F = (OFF_WARP + 16 * WSTRIDE) * 4;  // 231,744 B
    cudaFuncSetAttribute(k_fused, cudaFuncAttributeMaxDynamicSharedMemorySize, SMEM_F);

    k_init<<<256, 256>>>(Jp);
    k_fused<<<152, 512, SMEM_F>>>(y, W1, b1, W2, b2, W3, b3);
    k_ssq_part<<<256, 256>>>();
    k_ssq_final<<<1, 256>>>();
    k_kl<<<(B * 4) / 128, 128>>>(Wsym, lvd, out);
}